// round 2
// baseline (speedup 1.0000x reference)
#include <cuda_runtime.h>
#include <cstdint>
#include <cstdio>

#define B  1024
#define T  100
#define F  300
#define U  512
#define G  2048   /* 4*U */
#define NC 10
#define EPS 1e-3f

// ---------------- device scratch (static globals: allocation-free) ----------------
__device__ float g_A0[(size_t)B * T * G];   // LN(x@W0)*kg0+kb0 + b0, layout [B*T, G]
__device__ float g_z0 [B * G];              // h0s @ R0
__device__ float g_z1a[B * G];              // h0i @ W1
__device__ float g_z1b[B * G];              // h1s @ R1
__device__ float g_h0s[B * U];              // masked (carried) h, layer0
__device__ float g_h0i[B * U];              // unmasked h (input to layer1)
__device__ float g_h1s[B * U];
__device__ float g_c0 [B * U];
__device__ float g_c1 [B * U];
__device__ float g_out[B * U];              // masked-held final h1 (out_prev logic)

__device__ __forceinline__ float sigmf(float x) { return 1.0f / (1.0f + expf(-x)); }

__device__ __forceinline__ float f2tf32f(float x) {
    uint32_t r;
    asm("cvt.rna.tf32.f32 %0, %1;" : "=r"(r) : "f"(x));
    return __uint_as_float(r);
}

// ---------------- tf32x3 MMA GEMM: C[M,N] = A[M,K] @ B[K,N], row-major fp32 ------
// Error-compensated tf32: x = hi + lo, acc += Ahi*Bhi + Ahi*Blo + Alo*Bhi.
// CTA tile 128x64, BK=16, 8 warps (4x2), warp tile 32x32 of m16n8k8 MMAs.
#define BM 128
#define BN 64
#define BK 16
#define LDA 20   // padded smem stride for A
#define LDB 72   // padded smem stride for B

__global__ __launch_bounds__(256) void gemm_tf32x3(const float* __restrict__ A,
                                                   const float* __restrict__ Bm,
                                                   float* __restrict__ C,
                                                   int M, int N, int K)
{
    __shared__ float As[2][BM * LDA];   // [0]=hi, [1]=lo
    __shared__ float Bs[2][BK * LDB];

    const int tid  = threadIdx.x;
    const int lane = tid & 31;
    const int wid  = tid >> 5;
    const int wm   = wid >> 1;      // 0..3
    const int wn   = wid & 1;       // 0..1
    const int m0   = blockIdx.y * BM;
    const int n0   = blockIdx.x * BN;
    const int grp  = lane >> 2;     // 0..7
    const int tg   = lane & 3;      // 0..3

    float acc[2][4][4];
#pragma unroll
    for (int i = 0; i < 2; i++)
#pragma unroll
        for (int j = 0; j < 4; j++)
#pragma unroll
            for (int k = 0; k < 4; k++) acc[i][j][k] = 0.f;

    for (int k0 = 0; k0 < K; k0 += BK) {
        // --- load A tile 128x16 (float4 per thread, x2 rows) ---
        {
            const int c4  = tid & 3;       // float4 chunk in k
            const int row = tid >> 2;      // 0..63
            const bool kin = (k0 + c4 * 4) < K;   // K % 4 == 0, chunk all-in/out
#pragma unroll
            for (int r = 0; r < 2; r++) {
                const int m = row + r * 64;
                float4 v = make_float4(0.f, 0.f, 0.f, 0.f);
                if (kin) v = *(const float4*)(A + (size_t)(m0 + m) * K + k0 + c4 * 4);
                float* sh = &As[0][m * LDA + c4 * 4];
                float* sl = &As[1][m * LDA + c4 * 4];
                const float hx = f2tf32f(v.x), hy = f2tf32f(v.y),
                            hz = f2tf32f(v.z), hw = f2tf32f(v.w);
                sh[0] = hx; sh[1] = hy; sh[2] = hz; sh[3] = hw;
                sl[0] = f2tf32f(v.x - hx); sl[1] = f2tf32f(v.y - hy);
                sl[2] = f2tf32f(v.z - hz); sl[3] = f2tf32f(v.w - hw);
            }
        }
        // --- load B tile 16x64 (one float4 per thread) ---
        {
            const int n4 = tid & 15;       // float4 chunk in n
            const int kr = tid >> 4;       // 0..15
            float4 v = make_float4(0.f, 0.f, 0.f, 0.f);
            if (k0 + kr < K) v = *(const float4*)(Bm + (size_t)(k0 + kr) * N + n0 + n4 * 4);
            float* sh = &Bs[0][kr * LDB + n4 * 4];
            float* sl = &Bs[1][kr * LDB + n4 * 4];
            const float hx = f2tf32f(v.x), hy = f2tf32f(v.y),
                        hz = f2tf32f(v.z), hw = f2tf32f(v.w);
            sh[0] = hx; sh[1] = hy; sh[2] = hz; sh[3] = hw;
            sl[0] = f2tf32f(v.x - hx); sl[1] = f2tf32f(v.y - hy);
            sl[2] = f2tf32f(v.z - hz); sl[3] = f2tf32f(v.w - hw);
        }
        __syncthreads();

#pragma unroll
        for (int kk = 0; kk < 2; kk++) {
            uint32_t ah[2][4], al[2][4], bh[4][2], bl[4][2];
#pragma unroll
            for (int im = 0; im < 2; im++) {
                const int mb = wm * 32 + im * 16;
#pragma unroll
                for (int p = 0; p < 2; p++) {        // p: k-half (tg vs tg+4)
                    const int kc = kk * 8 + tg + p * 4;
                    ah[im][p * 2 + 0] = __float_as_uint(As[0][(mb + grp    ) * LDA + kc]);
                    ah[im][p * 2 + 1] = __float_as_uint(As[0][(mb + grp + 8) * LDA + kc]);
                    al[im][p * 2 + 0] = __float_as_uint(As[1][(mb + grp    ) * LDA + kc]);
                    al[im][p * 2 + 1] = __float_as_uint(As[1][(mb + grp + 8) * LDA + kc]);
                }
            }
            // NOTE: mma a-frag order for m16n8k8 is {a0,a1,a2,a3} =
            // {row(grp),k(tg)}, {row(grp+8),k(tg)}, {row(grp),k(tg+4)}, {row(grp+8),k(tg+4)}
            // which matches index layout [p*2+q] above.
#pragma unroll
            for (int jn = 0; jn < 4; jn++) {
                const int n = wn * 32 + jn * 8 + grp;
                bh[jn][0] = __float_as_uint(Bs[0][(kk * 8 + tg    ) * LDB + n]);
                bh[jn][1] = __float_as_uint(Bs[0][(kk * 8 + tg + 4) * LDB + n]);
                bl[jn][0] = __float_as_uint(Bs[1][(kk * 8 + tg    ) * LDB + n]);
                bl[jn][1] = __float_as_uint(Bs[1][(kk * 8 + tg + 4) * LDB + n]);
            }
#pragma unroll
            for (int im = 0; im < 2; im++)
#pragma unroll
                for (int jn = 0; jn < 4; jn++) {
                    // lo*hi and hi*lo first, hi*hi last (tiny terms first)
                    asm volatile(
                        "mma.sync.aligned.m16n8k8.row.col.f32.tf32.tf32.f32 "
                        "{%0,%1,%2,%3},{%4,%5,%6,%7},{%8,%9},{%0,%1,%2,%3};"
                        : "+f"(acc[im][jn][0]), "+f"(acc[im][jn][1]),
                          "+f"(acc[im][jn][2]), "+f"(acc[im][jn][3])
                        : "r"(al[im][0]), "r"(al[im][1]), "r"(al[im][2]), "r"(al[im][3]),
                          "r"(bh[jn][0]), "r"(bh[jn][1]));
                    asm volatile(
                        "mma.sync.aligned.m16n8k8.row.col.f32.tf32.tf32.f32 "
                        "{%0,%1,%2,%3},{%4,%5,%6,%7},{%8,%9},{%0,%1,%2,%3};"
                        : "+f"(acc[im][jn][0]), "+f"(acc[im][jn][1]),
                          "+f"(acc[im][jn][2]), "+f"(acc[im][jn][3])
                        : "r"(ah[im][0]), "r"(ah[im][1]), "r"(ah[im][2]), "r"(ah[im][3]),
                          "r"(bl[jn][0]), "r"(bl[jn][1]));
                    asm volatile(
                        "mma.sync.aligned.m16n8k8.row.col.f32.tf32.tf32.f32 "
                        "{%0,%1,%2,%3},{%4,%5,%6,%7},{%8,%9},{%0,%1,%2,%3};"
                        : "+f"(acc[im][jn][0]), "+f"(acc[im][jn][1]),
                          "+f"(acc[im][jn][2]), "+f"(acc[im][jn][3])
                        : "r"(ah[im][0]), "r"(ah[im][1]), "r"(ah[im][2]), "r"(ah[im][3]),
                          "r"(bh[jn][0]), "r"(bh[jn][1]));
                }
        }
        __syncthreads();
    }

    // --- epilogue: M,N are multiples of tile sizes for all our shapes ---
#pragma unroll
    for (int im = 0; im < 2; im++) {
        const int row0 = m0 + wm * 32 + im * 16 + grp;
#pragma unroll
        for (int jn = 0; jn < 4; jn++) {
            const int col = n0 + wn * 32 + jn * 8 + tg * 2;
            *(float2*)(C + (size_t)row0 * N + col)       = make_float2(acc[im][jn][0], acc[im][jn][1]);
            *(float2*)(C + (size_t)(row0 + 8) * N + col) = make_float2(acc[im][jn][2], acc[im][jn][3]);
        }
    }
}

// ---------------- row LayerNorm (in place on g_A0): z = LN(z)*gam + bet + bias ----
__global__ __launch_bounds__(256) void ln_rows_kernel(const float* __restrict__ gam,
                                                      const float* __restrict__ bet,
                                                      const float* __restrict__ bias)
{
    const size_t r = blockIdx.x;
    float* z = g_A0 + r * (size_t)G;
    const int tid = threadIdx.x, lane = tid & 31, w = tid >> 5;
    __shared__ float sh[2][8];
    __shared__ float bc[2];

    float v[8];
    float s = 0.f, ss = 0.f;
#pragma unroll
    for (int q = 0; q < 8; q++) {
        const float x = z[tid + q * 256];
        v[q] = x; s += x; ss += x * x;
    }
#pragma unroll
    for (int o = 16; o > 0; o >>= 1) {
        s  += __shfl_xor_sync(0xffffffffu, s, o);
        ss += __shfl_xor_sync(0xffffffffu, ss, o);
    }
    if (lane == 0) { sh[0][w] = s; sh[1][w] = ss; }
    __syncthreads();
    if (tid == 0) {
        float S = 0.f, SS = 0.f;
#pragma unroll
        for (int i = 0; i < 8; i++) { S += sh[0][i]; SS += sh[1][i]; }
        const float m = S / (float)G;
        bc[0] = m;
        bc[1] = rsqrtf(SS / (float)G - m * m + EPS);
    }
    __syncthreads();
    const float mean = bc[0], rstd = bc[1];
#pragma unroll
    for (int q = 0; q < 8; q++) {
        const int j = tid + q * 256;
        z[j] = (v[q] - mean) * rstd * gam[j] + bet[j] + bias[j];
    }
}

// ---------------- layer-0 cell: z = A0[t] + LN(z0)*rg+rb, gates, LN(c), mask -----
__global__ __launch_bounds__(256) void cell0_kernel(const float* __restrict__ rg,
                                                    const float* __restrict__ rb,
                                                    const float* __restrict__ sg,
                                                    const float* __restrict__ sb,
                                                    const int* __restrict__ mask, int t)
{
    const int b = blockIdx.x, tid = threadIdx.x, lane = tid & 31, w = tid >> 5;
    const float* z  = g_z0 + (size_t)b * G;
    const float* a0 = g_A0 + (size_t)(b * T + t) * G;
    __shared__ float sh[2][8];
    __shared__ float bc[2];

    float zr[2][4];
    float s = 0.f, ss = 0.f;
#pragma unroll
    for (int q = 0; q < 2; q++) {
        const int u = tid + q * 256;
#pragma unroll
        for (int gg = 0; gg < 4; gg++) {
            const float v = z[gg * U + u];
            zr[q][gg] = v; s += v; ss += v * v;
        }
    }
#pragma unroll
    for (int o = 16; o > 0; o >>= 1) {
        s  += __shfl_xor_sync(0xffffffffu, s, o);
        ss += __shfl_xor_sync(0xffffffffu, ss, o);
    }
    if (lane == 0) { sh[0][w] = s; sh[1][w] = ss; }
    __syncthreads();
    if (tid == 0) {
        float S = 0.f, SS = 0.f;
#pragma unroll
        for (int i = 0; i < 8; i++) { S += sh[0][i]; SS += sh[1][i]; }
        const float m = S / (float)G;
        bc[0] = m;
        bc[1] = rsqrtf(SS / (float)G - m * m + EPS);
    }
    __syncthreads();
    const float mean = bc[0], rstd = bc[1];

    float cn[2], zo[2];
    float s2 = 0.f, q2 = 0.f;
#pragma unroll
    for (int q = 0; q < 2; q++) {
        const int u = tid + q * 256;
        const float zi = (zr[q][0] - mean) * rstd * rg[u        ] + rb[u        ] + a0[u        ];
        const float zf = (zr[q][1] - mean) * rstd * rg[U     + u] + rb[U     + u] + a0[U     + u];
        const float zg = (zr[q][2] - mean) * rstd * rg[2 * U + u] + rb[2 * U + u] + a0[2 * U + u];
        zo[q]          = (zr[q][3] - mean) * rstd * rg[3 * U + u] + rb[3 * U + u] + a0[3 * U + u];
        const float c = g_c0[(size_t)b * U + u];
        const float v = sigmf(zf) * c + sigmf(zi) * tanhf(zg);
        cn[q] = v; s2 += v; q2 += v * v;
    }
#pragma unroll
    for (int o = 16; o > 0; o >>= 1) {
        s2 += __shfl_xor_sync(0xffffffffu, s2, o);
        q2 += __shfl_xor_sync(0xffffffffu, q2, o);
    }
    __syncthreads();   // protect sh/bc reuse
    if (lane == 0) { sh[0][w] = s2; sh[1][w] = q2; }
    __syncthreads();
    if (tid == 0) {
        float S = 0.f, P = 0.f;
#pragma unroll
        for (int i = 0; i < 8; i++) { S += sh[0][i]; P += sh[1][i]; }
        const float m = S / (float)U;
        bc[0] = m;
        bc[1] = rsqrtf(P / (float)U - m * m + EPS);
    }
    __syncthreads();
    const float m2 = bc[0], r2 = bc[1];
    const int msk = mask[b * T + t];
#pragma unroll
    for (int q = 0; q < 2; q++) {
        const int u = tid + q * 256;
        const float cl = (cn[q] - m2) * r2 * sg[u] + sb[u];
        const float hn = sigmf(zo[q]) * tanhf(cl);
        g_h0i[(size_t)b * U + u] = hn;                     // unmasked input to layer 1
        if (msk) { g_h0s[(size_t)b * U + u] = hn; g_c0[(size_t)b * U + u] = cl; }
    }
}

// ---------------- layer-1 cell: z = LN(z1a)*kg+kb + LN(z1b)*rg+rb + b1 -----------
__global__ __launch_bounds__(256) void cell1_kernel(const float* __restrict__ kg,
                                                    const float* __restrict__ kb,
                                                    const float* __restrict__ rg,
                                                    const float* __restrict__ rb,
                                                    const float* __restrict__ sg,
                                                    const float* __restrict__ sb,
                                                    const float* __restrict__ bias,
                                                    const int* __restrict__ mask, int t)
{
    const int b = blockIdx.x, tid = threadIdx.x, lane = tid & 31, w = tid >> 5;
    const float* za = g_z1a + (size_t)b * G;
    const float* zb = g_z1b + (size_t)b * G;
    __shared__ float sh[4][8];
    __shared__ float bc[4];

    float va[2][4], vb[2][4];
    float s1 = 0.f, p1 = 0.f, s2 = 0.f, p2 = 0.f;
#pragma unroll
    for (int q = 0; q < 2; q++) {
        const int u = tid + q * 256;
#pragma unroll
        for (int gg = 0; gg < 4; gg++) {
            const float x1 = za[gg * U + u];
            const float x2 = zb[gg * U + u];
            va[q][gg] = x1; vb[q][gg] = x2;
            s1 += x1; p1 += x1 * x1; s2 += x2; p2 += x2 * x2;
        }
    }
#pragma unroll
    for (int o = 16; o > 0; o >>= 1) {
        s1 += __shfl_xor_sync(0xffffffffu, s1, o);
        p1 += __shfl_xor_sync(0xffffffffu, p1, o);
        s2 += __shfl_xor_sync(0xffffffffu, s2, o);
        p2 += __shfl_xor_sync(0xffffffffu, p2, o);
    }
    if (lane == 0) { sh[0][w] = s1; sh[1][w] = p1; sh[2][w] = s2; sh[3][w] = p2; }
    __syncthreads();
    if (tid == 0) {
        float S1 = 0.f, P1 = 0.f, S2 = 0.f, P2 = 0.f;
#pragma unroll
        for (int i = 0; i < 8; i++) { S1 += sh[0][i]; P1 += sh[1][i]; S2 += sh[2][i]; P2 += sh[3][i]; }
        const float m1 = S1 / (float)G, m2 = S2 / (float)G;
        bc[0] = m1; bc[1] = rsqrtf(P1 / (float)G - m1 * m1 + EPS);
        bc[2] = m2; bc[3] = rsqrtf(P2 / (float)G - m2 * m2 + EPS);
    }
    __syncthreads();
    const float m1 = bc[0], r1 = bc[1], m2 = bc[2], r2 = bc[3];

    float cn[2], zo[2];
    float s3 = 0.f, p3 = 0.f;
#pragma unroll
    for (int q = 0; q < 2; q++) {
        const int u = tid + q * 256;
        float zg4[4];
#pragma unroll
        for (int gg = 0; gg < 4; gg++) {
            const int j = gg * U + u;
            zg4[gg] = (va[q][gg] - m1) * r1 * kg[j] + kb[j]
                    + (vb[q][gg] - m2) * r2 * rg[j] + rb[j] + bias[j];
        }
        const float c = g_c1[(size_t)b * U + u];
        const float v = sigmf(zg4[1]) * c + sigmf(zg4[0]) * tanhf(zg4[2]);
        cn[q] = v; zo[q] = zg4[3]; s3 += v; p3 += v * v;
    }
#pragma unroll
    for (int o = 16; o > 0; o >>= 1) {
        s3 += __shfl_xor_sync(0xffffffffu, s3, o);
        p3 += __shfl_xor_sync(0xffffffffu, p3, o);
    }
    __syncthreads();
    if (lane == 0) { sh[0][w] = s3; sh[1][w] = p3; }
    __syncthreads();
    if (tid == 0) {
        float S = 0.f, P = 0.f;
#pragma unroll
        for (int i = 0; i < 8; i++) { S += sh[0][i]; P += sh[1][i]; }
        const float m = S / (float)U;
        bc[0] = m;
        bc[1] = rsqrtf(P / (float)U - m * m + EPS);
    }
    __syncthreads();
    const float mc = bc[0], rc = bc[1];
    const int msk = mask[b * T + t];
#pragma unroll
    for (int q = 0; q < 2; q++) {
        const int u = tid + q * 256;
        const float cl = (cn[q] - mc) * rc * sg[u] + sb[u];
        const float hn = sigmf(zo[q]) * tanhf(cl);
        if (msk) {
            g_h1s[(size_t)b * U + u] = hn;
            g_c1 [(size_t)b * U + u] = cl;
            g_out[(size_t)b * U + u] = hn;   // out = where(mask, h1_new, out_prev)
        }
    }
}

// ---------------- init (zero states) -------------------------------------------
__global__ void init_kernel()
{
    const int i = blockIdx.x * 256 + threadIdx.x;
    if (i < B * U) {
        g_h0s[i] = 0.f; g_h1s[i] = 0.f;
        g_c0[i]  = 0.f; g_c1[i]  = 0.f;
        g_out[i] = 0.f;
    }
}

// ---------------- dense + softmax ----------------------------------------------
__global__ __launch_bounds__(256) void dense_kernel(const float* __restrict__ Wd,
                                                    const float* __restrict__ bd,
                                                    float* __restrict__ out)
{
    const int b = blockIdx.x, tid = threadIdx.x, lane = tid & 31, w = tid >> 5;
    float p[NC];
#pragma unroll
    for (int c = 0; c < NC; c++) p[c] = 0.f;
    for (int u = tid; u < U; u += 256) {
        const float h = g_out[(size_t)b * U + u];
#pragma unroll
        for (int c = 0; c < NC; c++) p[c] += h * Wd[u * NC + c];
    }
    __shared__ float sh[NC][8];
#pragma unroll
    for (int c = 0; c < NC; c++) {
        float v = p[c];
#pragma unroll
        for (int o = 16; o > 0; o >>= 1) v += __shfl_xor_sync(0xffffffffu, v, o);
        if (lane == 0) sh[c][w] = v;
    }
    __syncthreads();
    if (tid == 0) {
        float lg[NC];
        float mx = -1e30f;
#pragma unroll
        for (int c = 0; c < NC; c++) {
            float l = bd[c];
#pragma unroll
            for (int i = 0; i < 8; i++) l += sh[c][i];
            lg[c] = l;
            mx = fmaxf(mx, l);
        }
        float sum = 0.f;
#pragma unroll
        for (int c = 0; c < NC; c++) { lg[c] = expf(lg[c] - mx); sum += lg[c]; }
        const float inv = 1.f / sum;
#pragma unroll
        for (int c = 0; c < NC; c++) out[b * NC + c] = lg[c] * inv;
    }
}

// ---------------- launch --------------------------------------------------------
extern "C" void kernel_launch(void* const* d_in, const int* in_sizes, int n_in,
                              void* d_out, int out_size)
{
    const float* x    = (const float*)d_in[0];
    const int*   mask = (const int*)  d_in[1];
    const float* W0   = (const float*)d_in[2];
    const float* R0   = (const float*)d_in[3];
    const float* b0   = (const float*)d_in[4];
    const float* kg0  = (const float*)d_in[5];
    const float* kb0  = (const float*)d_in[6];
    const float* rg0  = (const float*)d_in[7];
    const float* rb0  = (const float*)d_in[8];
    const float* sg0  = (const float*)d_in[9];
    const float* sb0  = (const float*)d_in[10];
    const float* W1   = (const float*)d_in[11];
    const float* R1   = (const float*)d_in[12];
    const float* b1   = (const float*)d_in[13];
    const float* kg1  = (const float*)d_in[14];
    const float* kb1  = (const float*)d_in[15];
    const float* rg1  = (const float*)d_in[16];
    const float* rb1  = (const float*)d_in[17];
    const float* sg1  = (const float*)d_in[18];
    const float* sb1  = (const float*)d_in[19];
    const float* Wd   = (const float*)d_in[20];
    const float* bd   = (const float*)d_in[21];
    float* out = (float*)d_out;

    float *A0p, *z0p, *z1ap, *z1bp, *h0sp, *h0ip, *h1sp;
    cudaGetSymbolAddress((void**)&A0p,  g_A0);
    cudaGetSymbolAddress((void**)&z0p,  g_z0);
    cudaGetSymbolAddress((void**)&z1ap, g_z1a);
    cudaGetSymbolAddress((void**)&z1bp, g_z1b);
    cudaGetSymbolAddress((void**)&h0sp, g_h0s);
    cudaGetSymbolAddress((void**)&h0ip, g_h0i);
    cudaGetSymbolAddress((void**)&h1sp, g_h1s);

    init_kernel<<<(B * U + 255) / 256, 256>>>();

    // Precompute A0 = LN(x @ W0)*kg0 + kb0 + b0 for all (b, t)
    gemm_tf32x3<<<dim3(G / BN, (B * T) / BM), 256>>>(x, W0, A0p, B * T, G, F);
    ln_rows_kernel<<<B * T, 256>>>(kg0, kb0, b0);

    for (int t = 0; t < T; t++) {
        gemm_tf32x3<<<dim3(G / BN, B / BM), 256>>>(h0sp, R0, z0p, B, G, U);
        cell0_kernel<<<B, 256>>>(rg0, rb0, sg0, sb0, mask, t);
        gemm_tf32x3<<<dim3(G / BN, B / BM), 256>>>(h0ip, W1, z1ap, B, G, U);
        gemm_tf32x3<<<dim3(G / BN, B / BM), 256>>>(h1sp, R1, z1bp, B, G, U);
        cell1_kernel<<<B, 256>>>(kg1, kb1, rg1, rb1, sg1, sb1, b1, mask, t);
    }

    dense_kernel<<<B, 256>>>(Wd, bd, out);
}

// round 3
// speedup vs baseline: 1.0105x; 1.0105x over previous
#include <cuda_runtime.h>
#include <cstdint>

#define B  1024
#define T  100
#define F  300
#define FP 304     /* F padded to BK multiple */
#define U  512
#define G  2048    /* 4*U */
#define NC 10
#define EPS 1e-3f

#define BM 128
#define BN 64
#define BK 16
#define LDA 20
#define LDB 72
#define SMEM_GEMM ((2*2*BM*LDA + 2*2*BK*LDB) * 4)   /* 59392 B */

// ---------------- device scratch (static globals: allocation-free) ---------------
__device__ __align__(16) float g_A0[(size_t)B * T * G];
__device__ __align__(16) float g_xhi[(size_t)B * T * FP];
__device__ __align__(16) float g_xlo[(size_t)B * T * FP];
__device__ __align__(16) float g_W0hi[FP * G], g_W0lo[FP * G];
__device__ __align__(16) float g_R0hi[U * G],  g_R0lo[U * G];
__device__ __align__(16) float g_W1hi[U * G],  g_W1lo[U * G];
__device__ __align__(16) float g_R1hi[U * G],  g_R1lo[U * G];
__device__ __align__(16) float g_z0 [B * G], g_z1a[B * G], g_z1b[B * G];
__device__ __align__(16) float g_h0s_hi[B * U], g_h0s_lo[B * U];
__device__ __align__(16) float g_h0i_hi[B * U], g_h0i_lo[B * U];
__device__ __align__(16) float g_h1s_hi[B * U], g_h1s_lo[B * U];
__device__ __align__(16) float g_c0[B * U], g_c1[B * U], g_out[B * U];

__device__ __forceinline__ float sigmf(float x) { return 1.0f / (1.0f + expf(-x)); }

__device__ __forceinline__ float f2tf32f(float x) {
    uint32_t r;
    asm("cvt.rna.tf32.f32 %0, %1;" : "=r"(r) : "f"(x));
    return __uint_as_float(r);
}

__device__ __forceinline__ void cp16(uint32_t dst, const void* src) {
    asm volatile("cp.async.cg.shared.global [%0], [%1], 16;" :: "r"(dst), "l"(src));
}
__device__ __forceinline__ void cp_commit() { asm volatile("cp.async.commit_group;"); }
__device__ __forceinline__ void cp_wait0()  { asm volatile("cp.async.wait_group 0;"); }

// ---------------- split helpers (one-time prep) ----------------------------------
__global__ void split_mat(const float* __restrict__ s, float* __restrict__ hi,
                          float* __restrict__ lo, int n)
{
    int i = blockIdx.x * 256 + threadIdx.x;
    if (i < n) {
        const float v = s[i];
        const float h = f2tf32f(v);
        hi[i] = h; lo[i] = f2tf32f(v - h);
    }
}

__global__ void split_pad_rows(const float* __restrict__ s, float* __restrict__ hi,
                               float* __restrict__ lo, int nsrc, int ndst)
{
    int i = blockIdx.x * 256 + threadIdx.x;
    if (i < ndst) {
        const float v = (i < nsrc) ? s[i] : 0.f;
        const float h = f2tf32f(v);
        hi[i] = h; lo[i] = f2tf32f(v - h);
    }
}

__global__ void split_pad_cols(const float* __restrict__ s, float* __restrict__ hi,
                               float* __restrict__ lo, int rows, int csrc, int cdst)
{
    size_t i = (size_t)blockIdx.x * 256 + threadIdx.x;
    const size_t n = (size_t)rows * cdst;
    if (i < n) {
        const int r = (int)(i / cdst), c = (int)(i % cdst);
        const float v = (c < csrc) ? s[(size_t)r * csrc + c] : 0.f;
        const float h = f2tf32f(v);
        hi[i] = h; lo[i] = f2tf32f(v - h);
    }
}

__global__ void init_kernel()
{
    const size_t i = (size_t)blockIdx.x * 256 + threadIdx.x;
    if (i < (size_t)B * G) g_z0[i] = 0.f;
    if (i < (size_t)B * U) {
        g_h0s_hi[i] = 0.f; g_h0s_lo[i] = 0.f;
        g_h1s_hi[i] = 0.f; g_h1s_lo[i] = 0.f;
        g_c0[i] = 0.f; g_c1[i] = 0.f; g_out[i] = 0.f;
    }
}

// ---------------- pipelined tf32x3 GEMM (pre-split operands) ---------------------
// C[M,N] = A[M,K] @ B[K,N]. A,B given as (hi,lo) tf32-valued fp32 arrays.
// blockIdx.z picks one of up to 3 batched problems (same M,N,K).
struct Prob { const float *Ahi, *Alo, *Bhi, *Blo; float *C; };
struct GArgs { Prob p[3]; };

__global__ __launch_bounds__(256, 2) void gemm_split(GArgs ga, int N, int K)
{
    extern __shared__ float smem[];
    float* As = smem;                     // [stage][hl][BM*LDA]
    float* Bs = smem + 2 * 2 * BM * LDA;  // [stage][hl][BK*LDB]

    const Prob pr = ga.p[blockIdx.z];
    const int tid  = threadIdx.x;
    const int lane = tid & 31;
    const int wid  = tid >> 5;
    const int wm   = wid >> 1;            // 0..3
    const int wn   = wid & 1;             // 0..1
    const int m0   = blockIdx.y * BM;
    const int n0   = blockIdx.x * BN;
    const int grp  = lane >> 2;           // 0..7
    const int tg   = lane & 3;            // 0..3

    const uint32_t asB = (uint32_t)__cvta_generic_to_shared(As);
    const uint32_t bsB = (uint32_t)__cvta_generic_to_shared(Bs);

    auto issue = [&](int stage, int k0) {
        {
            const int c4 = tid & 3;        // k chunk
            const int rr = tid >> 2;       // 0..63
            const float* baseA[2] = { pr.Ahi, pr.Alo };
#pragma unroll
            for (int hl = 0; hl < 2; hl++)
#pragma unroll
                for (int r = 0; r < 2; r++) {
                    const int m = rr + r * 64;
                    const float* src = baseA[hl] + (size_t)(m0 + m) * K + k0 + c4 * 4;
                    cp16(asB + (uint32_t)((stage * 2 + hl) * BM * LDA + m * LDA + c4 * 4) * 4, src);
                }
        }
        {
            const int n4 = tid & 15;       // n chunk
            const int kr = tid >> 4;       // 0..15
            const float* baseB[2] = { pr.Bhi, pr.Blo };
#pragma unroll
            for (int hl = 0; hl < 2; hl++) {
                const float* src = baseB[hl] + (size_t)(k0 + kr) * N + n0 + n4 * 4;
                cp16(bsB + (uint32_t)((stage * 2 + hl) * BK * LDB + kr * LDB + n4 * 4) * 4, src);
            }
        }
        cp_commit();
    };

    float acc[2][4][4];
#pragma unroll
    for (int i = 0; i < 2; i++)
#pragma unroll
        for (int j = 0; j < 4; j++)
#pragma unroll
            for (int k = 0; k < 4; k++) acc[i][j][k] = 0.f;

    const int NIT = K / BK;
    issue(0, 0);

    for (int it = 0; it < NIT; ++it) {
        cp_wait0();
        __syncthreads();
        if (it + 1 < NIT) issue((it + 1) & 1, (it + 1) * BK);

        const int st = it & 1;
        const float* AsH = As + (st * 2 + 0) * BM * LDA;
        const float* AsL = As + (st * 2 + 1) * BM * LDA;
        const float* BsH = Bs + (st * 2 + 0) * BK * LDB;
        const float* BsL = Bs + (st * 2 + 1) * BK * LDB;

#pragma unroll
        for (int kk = 0; kk < 2; kk++) {
            uint32_t ah[2][4], al[2][4], bh[4][2], bl[4][2];
#pragma unroll
            for (int im = 0; im < 2; im++) {
                const int mb = wm * 32 + im * 16;
#pragma unroll
                for (int p = 0; p < 2; p++) {
                    const int kc = kk * 8 + tg + p * 4;
                    ah[im][p * 2 + 0] = __float_as_uint(AsH[(mb + grp    ) * LDA + kc]);
                    ah[im][p * 2 + 1] = __float_as_uint(AsH[(mb + grp + 8) * LDA + kc]);
                    al[im][p * 2 + 0] = __float_as_uint(AsL[(mb + grp    ) * LDA + kc]);
                    al[im][p * 2 + 1] = __float_as_uint(AsL[(mb + grp + 8) * LDA + kc]);
                }
            }
#pragma unroll
            for (int jn = 0; jn < 4; jn++) {
                const int n = wn * 32 + jn * 8 + grp;
                bh[jn][0] = __float_as_uint(BsH[(kk * 8 + tg    ) * LDB + n]);
                bh[jn][1] = __float_as_uint(BsH[(kk * 8 + tg + 4) * LDB + n]);
                bl[jn][0] = __float_as_uint(BsL[(kk * 8 + tg    ) * LDB + n]);
                bl[jn][1] = __float_as_uint(BsL[(kk * 8 + tg + 4) * LDB + n]);
            }
#pragma unroll
            for (int im = 0; im < 2; im++)
#pragma unroll
                for (int jn = 0; jn < 4; jn++) {
                    asm volatile(
                        "mma.sync.aligned.m16n8k8.row.col.f32.tf32.tf32.f32 "
                        "{%0,%1,%2,%3},{%4,%5,%6,%7},{%8,%9},{%0,%1,%2,%3};"
                        : "+f"(acc[im][jn][0]), "+f"(acc[im][jn][1]),
                          "+f"(acc[im][jn][2]), "+f"(acc[im][jn][3])
                        : "r"(al[im][0]), "r"(al[im][1]), "r"(al[im][2]), "r"(al[im][3]),
                          "r"(bh[jn][0]), "r"(bh[jn][1]));
                    asm volatile(
                        "mma.sync.aligned.m16n8k8.row.col.f32.tf32.tf32.f32 "
                        "{%0,%1,%2,%3},{%4,%5,%6,%7},{%8,%9},{%0,%1,%2,%3};"
                        : "+f"(acc[im][jn][0]), "+f"(acc[im][jn][1]),
                          "+f"(acc[im][jn][2]), "+f"(acc[im][jn][3])
                        : "r"(ah[im][0]), "r"(ah[im][1]), "r"(ah[im][2]), "r"(ah[im][3]),
                          "r"(bl[jn][0]), "r"(bl[jn][1]));
                    asm volatile(
                        "mma.sync.aligned.m16n8k8.row.col.f32.tf32.tf32.f32 "
                        "{%0,%1,%2,%3},{%4,%5,%6,%7},{%8,%9},{%0,%1,%2,%3};"
                        : "+f"(acc[im][jn][0]), "+f"(acc[im][jn][1]),
                          "+f"(acc[im][jn][2]), "+f"(acc[im][jn][3])
                        : "r"(ah[im][0]), "r"(ah[im][1]), "r"(ah[im][2]), "r"(ah[im][3]),
                          "r"(bh[jn][0]), "r"(bh[jn][1]));
                }
        }
    }

    // epilogue (M,N multiples of tile for all shapes here)
#pragma unroll
    for (int im = 0; im < 2; im++) {
        const int row0 = m0 + wm * 32 + im * 16 + grp;
#pragma unroll
        for (int jn = 0; jn < 4; jn++) {
            const int col = n0 + wn * 32 + jn * 8 + tg * 2;
            *(float2*)(pr.C + (size_t)row0 * N + col)       = make_float2(acc[im][jn][0], acc[im][jn][1]);
            *(float2*)(pr.C + (size_t)(row0 + 8) * N + col) = make_float2(acc[im][jn][2], acc[im][jn][3]);
        }
    }
}

// ---------------- row LayerNorm on g_A0: z = LN(z)*gam + bet + bias --------------
__global__ __launch_bounds__(256) void ln_rows_kernel(const float* __restrict__ gam,
                                                      const float* __restrict__ bet,
                                                      const float* __restrict__ bias)
{
    const size_t r = blockIdx.x;
    float* z = g_A0 + r * (size_t)G;
    const int tid = threadIdx.x, lane = tid & 31, w = tid >> 5;
    __shared__ float sh[2][8];
    __shared__ float bc[2];

    float v[8];
    float s = 0.f, ss = 0.f;
#pragma unroll
    for (int q = 0; q < 8; q++) {
        const float x = z[tid + q * 256];
        v[q] = x; s += x; ss += x * x;
    }
#pragma unroll
    for (int o = 16; o > 0; o >>= 1) {
        s  += __shfl_xor_sync(0xffffffffu, s, o);
        ss += __shfl_xor_sync(0xffffffffu, ss, o);
    }
    if (lane == 0) { sh[0][w] = s; sh[1][w] = ss; }
    __syncthreads();
    if (tid == 0) {
        float S = 0.f, SS = 0.f;
#pragma unroll
        for (int i = 0; i < 8; i++) { S += sh[0][i]; SS += sh[1][i]; }
        const float m = S / (float)G;
        bc[0] = m;
        bc[1] = rsqrtf(SS / (float)G - m * m + EPS);
    }
    __syncthreads();
    const float mean = bc[0], rstd = bc[1];
#pragma unroll
    for (int q = 0; q < 8; q++) {
        const int j = tid + q * 256;
        z[j] = (v[q] - mean) * rstd * gam[j] + bet[j] + bias[j];
    }
}

// ---------------- cell bodies ----------------------------------------------------
__device__ void cell0_body(int b, int t,
                           const float* __restrict__ rg, const float* __restrict__ rb,
                           const float* __restrict__ sg, const float* __restrict__ sb,
                           const int* __restrict__ mask)
{
    const int tid = threadIdx.x, lane = tid & 31, w = tid >> 5;
    const float* z  = g_z0 + (size_t)b * G;
    const float* a0 = g_A0 + (size_t)((size_t)b * T + t) * G;
    __shared__ float sh0[2][8];
    __shared__ float bc0[2];

    float zr[2][4];
    float s = 0.f, ss = 0.f;
#pragma unroll
    for (int q = 0; q < 2; q++) {
        const int u = tid + q * 256;
#pragma unroll
        for (int gg = 0; gg < 4; gg++) {
            const float v = z[gg * U + u];
            zr[q][gg] = v; s += v; ss += v * v;
        }
    }
#pragma unroll
    for (int o = 16; o > 0; o >>= 1) {
        s  += __shfl_xor_sync(0xffffffffu, s, o);
        ss += __shfl_xor_sync(0xffffffffu, ss, o);
    }
    if (lane == 0) { sh0[0][w] = s; sh0[1][w] = ss; }
    __syncthreads();
    if (tid == 0) {
        float S = 0.f, SS = 0.f;
#pragma unroll
        for (int i = 0; i < 8; i++) { S += sh0[0][i]; SS += sh0[1][i]; }
        const float m = S / (float)G;
        bc0[0] = m;
        bc0[1] = rsqrtf(SS / (float)G - m * m + EPS);
    }
    __syncthreads();
    const float mean = bc0[0], rstd = bc0[1];

    float cn[2], zo[2];
    float s2 = 0.f, q2 = 0.f;
#pragma unroll
    for (int q = 0; q < 2; q++) {
        const int u = tid + q * 256;
        const float zi = (zr[q][0] - mean) * rstd * rg[u        ] + rb[u        ] + a0[u        ];
        const float zf = (zr[q][1] - mean) * rstd * rg[U     + u] + rb[U     + u] + a0[U     + u];
        const float zg = (zr[q][2] - mean) * rstd * rg[2 * U + u] + rb[2 * U + u] + a0[2 * U + u];
        zo[q]          = (zr[q][3] - mean) * rstd * rg[3 * U + u] + rb[3 * U + u] + a0[3 * U + u];
        const float c = g_c0[(size_t)b * U + u];
        const float v = sigmf(zf) * c + sigmf(zi) * tanhf(zg);
        cn[q] = v; s2 += v; q2 += v * v;
    }
#pragma unroll
    for (int o = 16; o > 0; o >>= 1) {
        s2 += __shfl_xor_sync(0xffffffffu, s2, o);
        q2 += __shfl_xor_sync(0xffffffffu, q2, o);
    }
    __syncthreads();
    if (lane == 0) { sh0[0][w] = s2; sh0[1][w] = q2; }
    __syncthreads();
    if (tid == 0) {
        float S = 0.f, P = 0.f;
#pragma unroll
        for (int i = 0; i < 8; i++) { S += sh0[0][i]; P += sh0[1][i]; }
        const float m = S / (float)U;
        bc0[0] = m;
        bc0[1] = rsqrtf(P / (float)U - m * m + EPS);
    }
    __syncthreads();
    const float m2 = bc0[0], r2 = bc0[1];
    const int msk = mask[b * T + t];
#pragma unroll
    for (int q = 0; q < 2; q++) {
        const int u = tid + q * 256;
        const float cl = (cn[q] - m2) * r2 * sg[u] + sb[u];
        const float hn = sigmf(zo[q]) * tanhf(cl);
        const float hh = f2tf32f(hn);
        const float hl = f2tf32f(hn - hh);
        g_h0i_hi[(size_t)b * U + u] = hh;
        g_h0i_lo[(size_t)b * U + u] = hl;
        if (msk) {
            g_h0s_hi[(size_t)b * U + u] = hh;
            g_h0s_lo[(size_t)b * U + u] = hl;
            g_c0    [(size_t)b * U + u] = cl;
        }
    }
}

__device__ void cell1_body(int b, int t,
                           const float* __restrict__ kg, const float* __restrict__ kb,
                           const float* __restrict__ rg, const float* __restrict__ rb,
                           const float* __restrict__ sg, const float* __restrict__ sb,
                           const float* __restrict__ bias, const int* __restrict__ mask)
{
    const int tid = threadIdx.x, lane = tid & 31, w = tid >> 5;
    const float* za = g_z1a + (size_t)b * G;
    const float* zb = g_z1b + (size_t)b * G;
    __shared__ float sh1[4][8];
    __shared__ float bc1[4];

    float va[2][4], vb[2][4];
    float s1 = 0.f, p1 = 0.f, s2 = 0.f, p2 = 0.f;
#pragma unroll
    for (int q = 0; q < 2; q++) {
        const int u = tid + q * 256;
#pragma unroll
        for (int gg = 0; gg < 4; gg++) {
            const float x1 = za[gg * U + u];
            const float x2 = zb[gg * U + u];
            va[q][gg] = x1; vb[q][gg] = x2;
            s1 += x1; p1 += x1 * x1; s2 += x2; p2 += x2 * x2;
        }
    }
#pragma unroll
    for (int o = 16; o > 0; o >>= 1) {
        s1 += __shfl_xor_sync(0xffffffffu, s1, o);
        p1 += __shfl_xor_sync(0xffffffffu, p1, o);
        s2 += __shfl_xor_sync(0xffffffffu, s2, o);
        p2 += __shfl_xor_sync(0xffffffffu, p2, o);
    }
    if (lane == 0) { sh1[0][w] = s1; sh1[1][w] = p1; sh1[2][w] = s2; sh1[3][w] = p2; }
    __syncthreads();
    if (tid == 0) {
        float S1 = 0.f, P1 = 0.f, S2 = 0.f, P2 = 0.f;
#pragma unroll
        for (int i = 0; i < 8; i++) { S1 += sh1[0][i]; P1 += sh1[1][i]; S2 += sh1[2][i]; P2 += sh1[3][i]; }
        const float m1 = S1 / (float)G, m2 = S2 / (float)G;
        bc1[0] = m1; bc1[1] = rsqrtf(P1 / (float)G - m1 * m1 + EPS);
        bc1[2] = m2; bc1[3] = rsqrtf(P2 / (float)G - m2 * m2 + EPS);
    }
    __syncthreads();
    const float m1 = bc1[0], r1 = bc1[1], m2 = bc1[2], r2 = bc1[3];

    float cn[2], zo[2];
    float s3 = 0.f, p3 = 0.f;
#pragma unroll
    for (int q = 0; q < 2; q++) {
        const int u = tid + q * 256;
        float zg4[4];
#pragma unroll
        for (int gg = 0; gg < 4; gg++) {
            const int j = gg * U + u;
            zg4[gg] = (va[q][gg] - m1) * r1 * kg[j] + kb[j]
                    + (vb[q][gg] - m2) * r2 * rg[j] + rb[j] + bias[j];
        }
        const float c = g_c1[(size_t)b * U + u];
        const float v = sigmf(zg4[1]) * c + sigmf(zg4[0]) * tanhf(zg4[2]);
        cn[q] = v; zo[q] = zg4[3]; s3 += v; p3 += v * v;
    }
#pragma unroll
    for (int o = 16; o > 0; o >>= 1) {
        s3 += __shfl_xor_sync(0xffffffffu, s3, o);
        p3 += __shfl_xor_sync(0xffffffffu, p3, o);
    }
    __syncthreads();
    if (lane == 0) { sh1[0][w] = s3; sh1[1][w] = p3; }
    __syncthreads();
    if (tid == 0) {
        float S = 0.f, P = 0.f;
#pragma unroll
        for (int i = 0; i < 8; i++) { S += sh1[0][i]; P += sh1[1][i]; }
        const float m = S / (float)U;
        bc1[0] = m;
        bc1[1] = rsqrtf(P / (float)U - m * m + EPS);
    }
    __syncthreads();
    const float mc = bc1[0], rc = bc1[1];
    const int msk = mask[b * T + t];
#pragma unroll
    for (int q = 0; q < 2; q++) {
        const int u = tid + q * 256;
        const float cl = (cn[q] - mc) * rc * sg[u] + sb[u];
        const float hn = sigmf(zo[q]) * tanhf(cl);
        if (msk) {
            const float hh = f2tf32f(hn);
            g_h1s_hi[(size_t)b * U + u] = hh;
            g_h1s_lo[(size_t)b * U + u] = f2tf32f(hn - hh);
            g_c1    [(size_t)b * U + u] = cl;
            g_out   [(size_t)b * U + u] = hn;
        }
    }
}

// ---------------- kernels wrapping the bodies ------------------------------------
__global__ __launch_bounds__(256) void cell0_kernel(const float* rg, const float* rb,
                                                    const float* sg, const float* sb,
                                                    const int* mask, int t)
{
    cell0_body(blockIdx.x, t, rg, rb, sg, sb, mask);
}

__global__ __launch_bounds__(256) void cell1_kernel(const float* kg, const float* kb,
                                                    const float* rg, const float* rb,
                                                    const float* sg, const float* sb,
                                                    const float* bias, const int* mask, int t)
{
    cell1_body(blockIdx.x, t, kg, kb, rg, rb, sg, sb, bias, mask);
}

// fused: blocks [0,B) do cell1(t); blocks [B,2B) do cell0(t+1)
__global__ __launch_bounds__(256) void fused_cell_kernel(
    const float* rg0, const float* rb0, const float* sg0, const float* sb0,
    const float* kg1, const float* kb1, const float* rg1, const float* rb1,
    const float* sg1, const float* sb1, const float* b1,
    const int* mask, int t)
{
    if (blockIdx.x < B)
        cell1_body(blockIdx.x, t, kg1, kb1, rg1, rb1, sg1, sb1, b1, mask);
    else
        cell0_body(blockIdx.x - B, t + 1, rg0, rb0, sg0, sb0, mask);
}

// ---------------- dense + softmax ------------------------------------------------
__global__ __launch_bounds__(256) void dense_kernel(const float* __restrict__ Wd,
                                                    const float* __restrict__ bd,
                                                    float* __restrict__ out)
{
    const int b = blockIdx.x, tid = threadIdx.x, lane = tid & 31, w = tid >> 5;
    float p[NC];
#pragma unroll
    for (int c = 0; c < NC; c++) p[c] = 0.f;
    for (int u = tid; u < U; u += 256) {
        const float h = g_out[(size_t)b * U + u];
#pragma unroll
        for (int c = 0; c < NC; c++) p[c] += h * Wd[u * NC + c];
    }
    __shared__ float sh[NC][8];
#pragma unroll
    for (int c = 0; c < NC; c++) {
        float v = p[c];
#pragma unroll
        for (int o = 16; o > 0; o >>= 1) v += __shfl_xor_sync(0xffffffffu, v, o);
        if (lane == 0) sh[c][w] = v;
    }
    __syncthreads();
    if (tid == 0) {
        float lg[NC];
        float mx = -1e30f;
#pragma unroll
        for (int c = 0; c < NC; c++) {
            float l = bd[c];
#pragma unroll
            for (int i = 0; i < 8; i++) l += sh[c][i];
            lg[c] = l;
            mx = fmaxf(mx, l);
        }
        float sum = 0.f;
#pragma unroll
        for (int c = 0; c < NC; c++) { lg[c] = expf(lg[c] - mx); sum += lg[c]; }
        const float inv = 1.f / sum;
#pragma unroll
        for (int c = 0; c < NC; c++) out[b * NC + c] = lg[c] * inv;
    }
}

// ---------------- launch ----------------------------------------------------------
extern "C" void kernel_launch(void* const* d_in, const int* in_sizes, int n_in,
                              void* d_out, int out_size)
{
    const float* x    = (const float*)d_in[0];
    const int*   mask = (const int*)  d_in[1];
    const float* W0   = (const float*)d_in[2];
    const float* R0   = (const float*)d_in[3];
    const float* b0   = (const float*)d_in[4];
    const float* kg0  = (const float*)d_in[5];
    const float* kb0  = (const float*)d_in[6];
    const float* rg0  = (const float*)d_in[7];
    const float* rb0  = (const float*)d_in[8];
    const float* sg0  = (const float*)d_in[9];
    const float* sb0  = (const float*)d_in[10];
    const float* W1   = (const float*)d_in[11];
    const float* R1   = (const float*)d_in[12];
    const float* b1   = (const float*)d_in[13];
    const float* kg1  = (const float*)d_in[14];
    const float* kb1  = (const float*)d_in[15];
    const float* rg1  = (const float*)d_in[16];
    const float* rb1  = (const float*)d_in[17];
    const float* sg1  = (const float*)d_in[18];
    const float* sb1  = (const float*)d_in[19];
    const float* Wd   = (const float*)d_in[20];
    const float* bd   = (const float*)d_in[21];
    float* out = (float*)d_out;

    float *A0p, *z0p, *z1ap, *z1bp;
    float *xhi, *xlo, *W0hi, *W0lo, *R0hi, *R0lo, *W1hi, *W1lo, *R1hi, *R1lo;
    float *h0shi, *h0slo, *h0ihi, *h0ilo, *h1shi, *h1slo;
    cudaGetSymbolAddress((void**)&A0p,  g_A0);
    cudaGetSymbolAddress((void**)&z0p,  g_z0);
    cudaGetSymbolAddress((void**)&z1ap, g_z1a);
    cudaGetSymbolAddress((void**)&z1bp, g_z1b);
    cudaGetSymbolAddress((void**)&xhi,  g_xhi);
    cudaGetSymbolAddress((void**)&xlo,  g_xlo);
    cudaGetSymbolAddress((void**)&W0hi, g_W0hi);
    cudaGetSymbolAddress((void**)&W0lo, g_W0lo);
    cudaGetSymbolAddress((void**)&R0hi, g_R0hi);
    cudaGetSymbolAddress((void**)&R0lo, g_R0lo);
    cudaGetSymbolAddress((void**)&W1hi, g_W1hi);
    cudaGetSymbolAddress((void**)&W1lo, g_W1lo);
    cudaGetSymbolAddress((void**)&R1hi, g_R1hi);
    cudaGetSymbolAddress((void**)&R1lo, g_R1lo);
    cudaGetSymbolAddress((void**)&h0shi, g_h0s_hi);
    cudaGetSymbolAddress((void**)&h0slo, g_h0s_lo);
    cudaGetSymbolAddress((void**)&h0ihi, g_h0i_hi);
    cudaGetSymbolAddress((void**)&h0ilo, g_h0i_lo);
    cudaGetSymbolAddress((void**)&h1shi, g_h1s_hi);
    cudaGetSymbolAddress((void**)&h1slo, g_h1s_lo);

    cudaFuncSetAttribute(gemm_split, cudaFuncAttributeMaxDynamicSharedMemorySize, SMEM_GEMM);

    // one-time prep
    init_kernel<<<(B * G + 255) / 256, 256>>>();
    split_mat<<<(U * G + 255) / 256, 256>>>(R0, R0hi, R0lo, U * G);
    split_mat<<<(U * G + 255) / 256, 256>>>(W1, W1hi, W1lo, U * G);
    split_mat<<<(U * G + 255) / 256, 256>>>(R1, R1hi, R1lo, U * G);
    split_pad_rows<<<(FP * G + 255) / 256, 256>>>(W0, W0hi, W0lo, F * G, FP * G);
    {
        const size_t n = (size_t)B * T * FP;
        split_pad_cols<<<(unsigned)((n + 255) / 256), 256>>>(x, xhi, xlo, B * T, F, FP);
    }

    // precompute A0 = LN(x @ W0)*kg0 + kb0 + b0
    {
        GArgs a = {};
        a.p[0] = { xhi, xlo, W0hi, W0lo, A0p };
        gemm_split<<<dim3(G / BN, (B * T) / BM, 1), 256, SMEM_GEMM>>>(a, G, FP);
    }
    ln_rows_kernel<<<B * T, 256>>>(kg0, kb0, b0);

    // t = 0 prolog (z0(0) == 0, zeroed in init)
    cell0_kernel<<<B, 256>>>(rg0, rb0, sg0, sb0, mask, 0);

    for (int t = 0; t < T - 1; t++) {
        GArgs a = {};
        a.p[0] = { h0ihi, h0ilo, W1hi, W1lo, z1ap };   // z1a(t)
        a.p[1] = { h1shi, h1slo, R1hi, R1lo, z1bp };   // z1b(t)
        a.p[2] = { h0shi, h0slo, R0hi, R0lo, z0p  };   // z0(t+1)
        gemm_split<<<dim3(G / BN, B / BM, 3), 256, SMEM_GEMM>>>(a, G, U);
        fused_cell_kernel<<<2 * B, 256>>>(rg0, rb0, sg0, sb0,
                                          kg1, kb1, rg1, rb1, sg1, sb1, b1, mask, t);
    }

    // t = T-1 epilog
    {
        GArgs a = {};
        a.p[0] = { h0ihi, h0ilo, W1hi, W1lo, z1ap };
        a.p[1] = { h1shi, h1slo, R1hi, R1lo, z1bp };
        gemm_split<<<dim3(G / BN, B / BM, 2), 256, SMEM_GEMM>>>(a, G, U);
        cell1_kernel<<<B, 256>>>(kg1, kb1, rg1, rb1, sg1, sb1, b1, mask, T - 1);
    }

    dense_kernel<<<B, 256>>>(Wd, bd, out);
}

// round 4
// speedup vs baseline: 1.0129x; 1.0024x over previous
#include <cuda_runtime.h>
#include <cstdint>

#define B  1024
#define T  100
#define F  300
#define FP 304     /* F padded to BK multiple */
#define U  512
#define G  2048    /* 4*U */
#define NC 10
#define EPS 1e-3f

#define BM 128
#define BN 64
#define BK 16
#define LDA 20
#define LDB 72
#define SMEM_GEMM ((2*2*BM*LDA + 2*2*BK*LDB) * 4)   /* 59392 B */

// ---------------- device scratch (static globals: allocation-free) ---------------
__device__ __align__(16) float g_A0[(size_t)B * T * G];
__device__ __align__(16) float g_xhi[(size_t)B * T * FP];
__device__ __align__(16) float g_xlo[(size_t)B * T * FP];
__device__ __align__(16) float g_W0hi[FP * G], g_W0lo[FP * G];
__device__ __align__(16) float g_R0hi[U * G],  g_R0lo[U * G];
__device__ __align__(16) float g_W1hi[U * G],  g_W1lo[U * G];
__device__ __align__(16) float g_R1hi[U * G],  g_R1lo[U * G];
__device__ __align__(16) float g_z0 [B * G], g_z1a[B * G], g_z1b[B * G];
__device__ __align__(16) float g_h0s_hi[B * U], g_h0s_lo[B * U];
__device__ __align__(16) float g_h0i_hi[B * U], g_h0i_lo[B * U];
__device__ __align__(16) float g_h1s_hi[B * U], g_h1s_lo[B * U];
__device__ __align__(16) float g_c0[B * U], g_c1[B * U], g_out[B * U];

__device__ __forceinline__ float sigmf(float x) { return 1.0f / (1.0f + expf(-x)); }

__device__ __forceinline__ float f2tf32f(float x) {
    uint32_t r;
    asm("cvt.rna.tf32.f32 %0, %1;" : "=r"(r) : "f"(x));
    return __uint_as_float(r);
}

__device__ __forceinline__ void cp16(uint32_t dst, const void* src) {
    asm volatile("cp.async.cg.shared.global [%0], [%1], 16;" :: "r"(dst), "l"(src));
}
__device__ __forceinline__ void cp_commit() { asm volatile("cp.async.commit_group;"); }
__device__ __forceinline__ void cp_wait0()  { asm volatile("cp.async.wait_group 0;"); }

// ---------------- split helpers (one-time prep) ----------------------------------
__global__ void split_mat(const float* __restrict__ s, float* __restrict__ hi,
                          float* __restrict__ lo, int n)
{
    int i = blockIdx.x * 256 + threadIdx.x;
    if (i < n) {
        const float v = s[i];
        const float h = f2tf32f(v);
        hi[i] = h; lo[i] = f2tf32f(v - h);
    }
}

__global__ void split_pad_rows(const float* __restrict__ s, float* __restrict__ hi,
                               float* __restrict__ lo, int nsrc, int ndst)
{
    int i = blockIdx.x * 256 + threadIdx.x;
    if (i < ndst) {
        const float v = (i < nsrc) ? s[i] : 0.f;
        const float h = f2tf32f(v);
        hi[i] = h; lo[i] = f2tf32f(v - h);
    }
}

__global__ void split_pad_cols(const float* __restrict__ s, float* __restrict__ hi,
                               float* __restrict__ lo, int rows, int csrc, int cdst)
{
    size_t i = (size_t)blockIdx.x * 256 + threadIdx.x;
    const size_t n = (size_t)rows * cdst;
    if (i < n) {
        const int r = (int)(i / cdst), c = (int)(i % cdst);
        const float v = (c < csrc) ? s[(size_t)r * csrc + c] : 0.f;
        const float h = f2tf32f(v);
        hi[i] = h; lo[i] = f2tf32f(v - h);
    }
}

__global__ void init_kernel()
{
    const size_t i = (size_t)blockIdx.x * 256 + threadIdx.x;
    if (i < (size_t)B * G) g_z0[i] = 0.f;
    if (i < (size_t)B * U) {
        g_h0s_hi[i] = 0.f; g_h0s_lo[i] = 0.f;
        g_h1s_hi[i] = 0.f; g_h1s_lo[i] = 0.f;
        g_c0[i] = 0.f; g_c1[i] = 0.f; g_out[i] = 0.f;
    }
}

// ---------------- pipelined tf32x3 GEMM (pre-split operands) ---------------------
// C[M,N] = A[M,K] @ B[K,N]. A,B given as (hi,lo) tf32-valued fp32 arrays.
// blockIdx.z picks one of up to 3 batched problems (same M,N,K).
struct Prob { const float *Ahi, *Alo, *Bhi, *Blo; float *C; };
struct GArgs { Prob p[3]; };

__global__ __launch_bounds__(256, 2) void gemm_split(GArgs ga, int N, int K)
{
    extern __shared__ float smem[];
    float* As = smem;                     // [stage][hl][BM*LDA]
    float* Bs = smem + 2 * 2 * BM * LDA;  // [stage][hl][BK*LDB]

    const Prob pr = ga.p[blockIdx.z];
    const int tid  = threadIdx.x;
    const int lane = tid & 31;
    const int wid  = tid >> 5;
    const int wm   = wid >> 1;            // 0..3
    const int wn   = wid & 1;             // 0..1
    const int m0   = blockIdx.y * BM;
    const int n0   = blockIdx.x * BN;
    const int grp  = lane >> 2;           // 0..7
    const int tg   = lane & 3;            // 0..3

    const uint32_t asB = (uint32_t)__cvta_generic_to_shared(As);
    const uint32_t bsB = (uint32_t)__cvta_generic_to_shared(Bs);

    auto issue = [&](int stage, int k0) {
        {
            const int c4 = tid & 3;        // k chunk
            const int rr = tid >> 2;       // 0..63
            const float* baseA[2] = { pr.Ahi, pr.Alo };
#pragma unroll
            for (int hl = 0; hl < 2; hl++)
#pragma unroll
                for (int r = 0; r < 2; r++) {
                    const int m = rr + r * 64;
                    const float* src = baseA[hl] + (size_t)(m0 + m) * K + k0 + c4 * 4;
                    cp16(asB + (uint32_t)((stage * 2 + hl) * BM * LDA + m * LDA + c4 * 4) * 4, src);
                }
        }
        {
            const int n4 = tid & 15;       // n chunk
            const int kr = tid >> 4;       // 0..15
            const float* baseB[2] = { pr.Bhi, pr.Blo };
#pragma unroll
            for (int hl = 0; hl < 2; hl++) {
                const float* src = baseB[hl] + (size_t)(k0 + kr) * N + n0 + n4 * 4;
                cp16(bsB + (uint32_t)((stage * 2 + hl) * BK * LDB + kr * LDB + n4 * 4) * 4, src);
            }
        }
        cp_commit();
    };

    float acc[2][4][4];
#pragma unroll
    for (int i = 0; i < 2; i++)
#pragma unroll
        for (int j = 0; j < 4; j++)
#pragma unroll
            for (int k = 0; k < 4; k++) acc[i][j][k] = 0.f;

    const int NIT = K / BK;
    issue(0, 0);

    for (int it = 0; it < NIT; ++it) {
        cp_wait0();
        __syncthreads();
        if (it + 1 < NIT) issue((it + 1) & 1, (it + 1) * BK);

        const int st = it & 1;
        const float* AsH = As + (st * 2 + 0) * BM * LDA;
        const float* AsL = As + (st * 2 + 1) * BM * LDA;
        const float* BsH = Bs + (st * 2 + 0) * BK * LDB;
        const float* BsL = Bs + (st * 2 + 1) * BK * LDB;

#pragma unroll
        for (int kk = 0; kk < 2; kk++) {
            uint32_t ah[2][4], al[2][4], bh[4][2], bl[4][2];
#pragma unroll
            for (int im = 0; im < 2; im++) {
                const int mb = wm * 32 + im * 16;
#pragma unroll
                for (int p = 0; p < 2; p++) {
                    const int kc = kk * 8 + tg + p * 4;
                    ah[im][p * 2 + 0] = __float_as_uint(AsH[(mb + grp    ) * LDA + kc]);
                    ah[im][p * 2 + 1] = __float_as_uint(AsH[(mb + grp + 8) * LDA + kc]);
                    al[im][p * 2 + 0] = __float_as_uint(AsL[(mb + grp    ) * LDA + kc]);
                    al[im][p * 2 + 1] = __float_as_uint(AsL[(mb + grp + 8) * LDA + kc]);
                }
            }
#pragma unroll
            for (int jn = 0; jn < 4; jn++) {
                const int n = wn * 32 + jn * 8 + grp;
                bh[jn][0] = __float_as_uint(BsH[(kk * 8 + tg    ) * LDB + n]);
                bh[jn][1] = __float_as_uint(BsH[(kk * 8 + tg + 4) * LDB + n]);
                bl[jn][0] = __float_as_uint(BsL[(kk * 8 + tg    ) * LDB + n]);
                bl[jn][1] = __float_as_uint(BsL[(kk * 8 + tg + 4) * LDB + n]);
            }
#pragma unroll
            for (int im = 0; im < 2; im++)
#pragma unroll
                for (int jn = 0; jn < 4; jn++) {
                    asm volatile(
                        "mma.sync.aligned.m16n8k8.row.col.f32.tf32.tf32.f32 "
                        "{%0,%1,%2,%3},{%4,%5,%6,%7},{%8,%9},{%0,%1,%2,%3};"
                        : "+f"(acc[im][jn][0]), "+f"(acc[im][jn][1]),
                          "+f"(acc[im][jn][2]), "+f"(acc[im][jn][3])
                        : "r"(al[im][0]), "r"(al[im][1]), "r"(al[im][2]), "r"(al[im][3]),
                          "r"(bh[jn][0]), "r"(bh[jn][1]));
                    asm volatile(
                        "mma.sync.aligned.m16n8k8.row.col.f32.tf32.tf32.f32 "
                        "{%0,%1,%2,%3},{%4,%5,%6,%7},{%8,%9},{%0,%1,%2,%3};"
                        : "+f"(acc[im][jn][0]), "+f"(acc[im][jn][1]),
                          "+f"(acc[im][jn][2]), "+f"(acc[im][jn][3])
                        : "r"(ah[im][0]), "r"(ah[im][1]), "r"(ah[im][2]), "r"(ah[im][3]),
                          "r"(bl[jn][0]), "r"(bl[jn][1]));
                    asm volatile(
                        "mma.sync.aligned.m16n8k8.row.col.f32.tf32.tf32.f32 "
                        "{%0,%1,%2,%3},{%4,%5,%6,%7},{%8,%9},{%0,%1,%2,%3};"
                        : "+f"(acc[im][jn][0]), "+f"(acc[im][jn][1]),
                          "+f"(acc[im][jn][2]), "+f"(acc[im][jn][3])
                        : "r"(ah[im][0]), "r"(ah[im][1]), "r"(ah[im][2]), "r"(ah[im][3]),
                          "r"(bh[jn][0]), "r"(bh[jn][1]));
                }
        }
    }

    // epilogue (M,N multiples of tile for all shapes here)
#pragma unroll
    for (int im = 0; im < 2; im++) {
        const int row0 = m0 + wm * 32 + im * 16 + grp;
#pragma unroll
        for (int jn = 0; jn < 4; jn++) {
            const int col = n0 + wn * 32 + jn * 8 + tg * 2;
            *(float2*)(pr.C + (size_t)row0 * N + col)       = make_float2(acc[im][jn][0], acc[im][jn][1]);
            *(float2*)(pr.C + (size_t)(row0 + 8) * N + col) = make_float2(acc[im][jn][2], acc[im][jn][3]);
        }
    }
}

// ---------------- row LayerNorm on g_A0: z = LN(z)*gam + bet + bias --------------
__global__ __launch_bounds__(256) void ln_rows_kernel(const float* __restrict__ gam,
                                                      const float* __restrict__ bet,
                                                      const float* __restrict__ bias)
{
    const size_t r = blockIdx.x;
    float* z = g_A0 + r * (size_t)G;
    const int tid = threadIdx.x, lane = tid & 31, w = tid >> 5;
    __shared__ float sh[2][8];
    __shared__ float bc[2];

    float v[8];
    float s = 0.f, ss = 0.f;
#pragma unroll
    for (int q = 0; q < 8; q++) {
        const float x = z[tid + q * 256];
        v[q] = x; s += x; ss += x * x;
    }
#pragma unroll
    for (int o = 16; o > 0; o >>= 1) {
        s  += __shfl_xor_sync(0xffffffffu, s, o);
        ss += __shfl_xor_sync(0xffffffffu, ss, o);
    }
    if (lane == 0) { sh[0][w] = s; sh[1][w] = ss; }
    __syncthreads();
    if (tid == 0) {
        float S = 0.f, SS = 0.f;
#pragma unroll
        for (int i = 0; i < 8; i++) { S += sh[0][i]; SS += sh[1][i]; }
        const float m = S / (float)G;
        bc[0] = m;
        bc[1] = rsqrtf(SS / (float)G - m * m + EPS);
    }
    __syncthreads();
    const float mean = bc[0], rstd = bc[1];
#pragma unroll
    for (int q = 0; q < 8; q++) {
        const int j = tid + q * 256;
        z[j] = (v[q] - mean) * rstd * gam[j] + bet[j] + bias[j];
    }
}

// ---------------- cell bodies ----------------------------------------------------
__device__ void cell0_body(int b, int t,
                           const float* __restrict__ rg, const float* __restrict__ rb,
                           const float* __restrict__ sg, const float* __restrict__ sb,
                           const int* __restrict__ mask)
{
    const int tid = threadIdx.x, lane = tid & 31, w = tid >> 5;
    const float* z  = g_z0 + (size_t)b * G;
    const float* a0 = g_A0 + (size_t)((size_t)b * T + t) * G;
    __shared__ float sh0[2][8];
    __shared__ float bc0[2];

    float zr[2][4];
    float s = 0.f, ss = 0.f;
#pragma unroll
    for (int q = 0; q < 2; q++) {
        const int u = tid + q * 256;
#pragma unroll
        for (int gg = 0; gg < 4; gg++) {
            const float v = z[gg * U + u];
            zr[q][gg] = v; s += v; ss += v * v;
        }
    }
#pragma unroll
    for (int o = 16; o > 0; o >>= 1) {
        s  += __shfl_xor_sync(0xffffffffu, s, o);
        ss += __shfl_xor_sync(0xffffffffu, ss, o);
    }
    if (lane == 0) { sh0[0][w] = s; sh0[1][w] = ss; }
    __syncthreads();
    if (tid == 0) {
        float S = 0.f, SS = 0.f;
#pragma unroll
        for (int i = 0; i < 8; i++) { S += sh0[0][i]; SS += sh0[1][i]; }
        const float m = S / (float)G;
        bc0[0] = m;
        bc0[1] = rsqrtf(SS / (float)G - m * m + EPS);
    }
    __syncthreads();
    const float mean = bc0[0], rstd = bc0[1];

    float cn[2], zo[2];
    float s2 = 0.f, q2 = 0.f;
#pragma unroll
    for (int q = 0; q < 2; q++) {
        const int u = tid + q * 256;
        const float zi = (zr[q][0] - mean) * rstd * rg[u        ] + rb[u        ] + a0[u        ];
        const float zf = (zr[q][1] - mean) * rstd * rg[U     + u] + rb[U     + u] + a0[U     + u];
        const float zg = (zr[q][2] - mean) * rstd * rg[2 * U + u] + rb[2 * U + u] + a0[2 * U + u];
        zo[q]          = (zr[q][3] - mean) * rstd * rg[3 * U + u] + rb[3 * U + u] + a0[3 * U + u];
        const float c = g_c0[(size_t)b * U + u];
        const float v = sigmf(zf) * c + sigmf(zi) * tanhf(zg);
        cn[q] = v; s2 += v; q2 += v * v;
    }
#pragma unroll
    for (int o = 16; o > 0; o >>= 1) {
        s2 += __shfl_xor_sync(0xffffffffu, s2, o);
        q2 += __shfl_xor_sync(0xffffffffu, q2, o);
    }
    __syncthreads();
    if (lane == 0) { sh0[0][w] = s2; sh0[1][w] = q2; }
    __syncthreads();
    if (tid == 0) {
        float S = 0.f, P = 0.f;
#pragma unroll
        for (int i = 0; i < 8; i++) { S += sh0[0][i]; P += sh0[1][i]; }
        const float m = S / (float)U;
        bc0[0] = m;
        bc0[1] = rsqrtf(P / (float)U - m * m + EPS);
    }
    __syncthreads();
    const float m2 = bc0[0], r2 = bc0[1];
    const int msk = mask[b * T + t];
#pragma unroll
    for (int q = 0; q < 2; q++) {
        const int u = tid + q * 256;
        const float cl = (cn[q] - m2) * r2 * sg[u] + sb[u];
        const float hn = sigmf(zo[q]) * tanhf(cl);
        const float hh = f2tf32f(hn);
        const float hl = f2tf32f(hn - hh);
        g_h0i_hi[(size_t)b * U + u] = hh;
        g_h0i_lo[(size_t)b * U + u] = hl;
        if (msk) {
            g_h0s_hi[(size_t)b * U + u] = hh;
            g_h0s_lo[(size_t)b * U + u] = hl;
            g_c0    [(size_t)b * U + u] = cl;
        }
    }
}

__device__ void cell1_body(int b, int t,
                           const float* __restrict__ kg, const float* __restrict__ kb,
                           const float* __restrict__ rg, const float* __restrict__ rb,
                           const float* __restrict__ sg, const float* __restrict__ sb,
                           const float* __restrict__ bias, const int* __restrict__ mask)
{
    const int tid = threadIdx.x, lane = tid & 31, w = tid >> 5;
    const float* za = g_z1a + (size_t)b * G;
    const float* zb = g_z1b + (size_t)b * G;
    __shared__ float sh1[4][8];
    __shared__ float bc1[4];

    float va[2][4], vb[2][4];
    float s1 = 0.f, p1 = 0.f, s2 = 0.f, p2 = 0.f;
#pragma unroll
    for (int q = 0; q < 2; q++) {
        const int u = tid + q * 256;
#pragma unroll
        for (int gg = 0; gg < 4; gg++) {
            const float x1 = za[gg * U + u];
            const float x2 = zb[gg * U + u];
            va[q][gg] = x1; vb[q][gg] = x2;
            s1 += x1; p1 += x1 * x1; s2 += x2; p2 += x2 * x2;
        }
    }
#pragma unroll
    for (int o = 16; o > 0; o >>= 1) {
        s1 += __shfl_xor_sync(0xffffffffu, s1, o);
        p1 += __shfl_xor_sync(0xffffffffu, p1, o);
        s2 += __shfl_xor_sync(0xffffffffu, s2, o);
        p2 += __shfl_xor_sync(0xffffffffu, p2, o);
    }
    if (lane == 0) { sh1[0][w] = s1; sh1[1][w] = p1; sh1[2][w] = s2; sh1[3][w] = p2; }
    __syncthreads();
    if (tid == 0) {
        float S1 = 0.f, P1 = 0.f, S2 = 0.f, P2 = 0.f;
#pragma unroll
        for (int i = 0; i < 8; i++) { S1 += sh1[0][i]; P1 += sh1[1][i]; S2 += sh1[2][i]; P2 += sh1[3][i]; }
        const float m1 = S1 / (float)G, m2 = S2 / (float)G;
        bc1[0] = m1; bc1[1] = rsqrtf(P1 / (float)G - m1 * m1 + EPS);
        bc1[2] = m2; bc1[3] = rsqrtf(P2 / (float)G - m2 * m2 + EPS);
    }
    __syncthreads();
    const float m1 = bc1[0], r1 = bc1[1], m2 = bc1[2], r2 = bc1[3];

    float cn[2], zo[2];
    float s3 = 0.f, p3 = 0.f;
#pragma unroll
    for (int q = 0; q < 2; q++) {
        const int u = tid + q * 256;
        float zg4[4];
#pragma unroll
        for (int gg = 0; gg < 4; gg++) {
            const int j = gg * U + u;
            zg4[gg] = (va[q][gg] - m1) * r1 * kg[j] + kb[j]
                    + (vb[q][gg] - m2) * r2 * rg[j] + rb[j] + bias[j];
        }
        const float c = g_c1[(size_t)b * U + u];
        const float v = sigmf(zg4[1]) * c + sigmf(zg4[0]) * tanhf(zg4[2]);
        cn[q] = v; zo[q] = zg4[3]; s3 += v; p3 += v * v;
    }
#pragma unroll
    for (int o = 16; o > 0; o >>= 1) {
        s3 += __shfl_xor_sync(0xffffffffu, s3, o);
        p3 += __shfl_xor_sync(0xffffffffu, p3, o);
    }
    __syncthreads();
    if (lane == 0) { sh1[0][w] = s3; sh1[1][w] = p3; }
    __syncthreads();
    if (tid == 0) {
        float S = 0.f, P = 0.f;
#pragma unroll
        for (int i = 0; i < 8; i++) { S += sh1[0][i]; P += sh1[1][i]; }
        const float m = S / (float)U;
        bc1[0] = m;
        bc1[1] = rsqrtf(P / (float)U - m * m + EPS);
    }
    __syncthreads();
    const float mc = bc1[0], rc = bc1[1];
    const int msk = mask[b * T + t];
#pragma unroll
    for (int q = 0; q < 2; q++) {
        const int u = tid + q * 256;
        const float cl = (cn[q] - mc) * rc * sg[u] + sb[u];
        const float hn = sigmf(zo[q]) * tanhf(cl);
        if (msk) {
            const float hh = f2tf32f(hn);
            g_h1s_hi[(size_t)b * U + u] = hh;
            g_h1s_lo[(size_t)b * U + u] = f2tf32f(hn - hh);
            g_c1    [(size_t)b * U + u] = cl;
            g_out   [(size_t)b * U + u] = hn;
        }
    }
}

// ---------------- kernels wrapping the bodies ------------------------------------
__global__ __launch_bounds__(256) void cell0_kernel(const float* rg, const float* rb,
                                                    const float* sg, const float* sb,
                                                    const int* mask, int t)
{
    cell0_body(blockIdx.x, t, rg, rb, sg, sb, mask);
}

__global__ __launch_bounds__(256) void cell1_kernel(const float* kg, const float* kb,
                                                    const float* rg, const float* rb,
                                                    const float* sg, const float* sb,
                                                    const float* bias, const int* mask, int t)
{
    cell1_body(blockIdx.x, t, kg, kb, rg, rb, sg, sb, bias, mask);
}

// fused: blocks [0,B) do cell1(t); blocks [B,2B) do cell0(t+1)
__global__ __launch_bounds__(256) void fused_cell_kernel(
    const float* rg0, const float* rb0, const float* sg0, const float* sb0,
    const float* kg1, const float* kb1, const float* rg1, const float* rb1,
    const float* sg1, const float* sb1, const float* b1,
    const int* mask, int t)
{
    if (blockIdx.x < B)
        cell1_body(blockIdx.x, t, kg1, kb1, rg1, rb1, sg1, sb1, b1, mask);
    else
        cell0_body(blockIdx.x - B, t + 1, rg0, rb0, sg0, sb0, mask);
}

// ---------------- dense + softmax ------------------------------------------------
__global__ __launch_bounds__(256) void dense_kernel(const float* __restrict__ Wd,
                                                    const float* __restrict__ bd,
                                                    float* __restrict__ out)
{
    const int b = blockIdx.x, tid = threadIdx.x, lane = tid & 31, w = tid >> 5;
    float p[NC];
#pragma unroll
    for (int c = 0; c < NC; c++) p[c] = 0.f;
    for (int u = tid; u < U; u += 256) {
        const float h = g_out[(size_t)b * U + u];
#pragma unroll
        for (int c = 0; c < NC; c++) p[c] += h * Wd[u * NC + c];
    }
    __shared__ float sh[NC][8];
#pragma unroll
    for (int c = 0; c < NC; c++) {
        float v = p[c];
#pragma unroll
        for (int o = 16; o > 0; o >>= 1) v += __shfl_xor_sync(0xffffffffu, v, o);
        if (lane == 0) sh[c][w] = v;
    }
    __syncthreads();
    if (tid == 0) {
        float lg[NC];
        float mx = -1e30f;
#pragma unroll
        for (int c = 0; c < NC; c++) {
            float l = bd[c];
#pragma unroll
            for (int i = 0; i < 8; i++) l += sh[c][i];
            lg[c] = l;
            mx = fmaxf(mx, l);
        }
        float sum = 0.f;
#pragma unroll
        for (int c = 0; c < NC; c++) { lg[c] = expf(lg[c] - mx); sum += lg[c]; }
        const float inv = 1.f / sum;
#pragma unroll
        for (int c = 0; c < NC; c++) out[b * NC + c] = lg[c] * inv;
    }
}

// ---------------- launch ----------------------------------------------------------
extern "C" void kernel_launch(void* const* d_in, const int* in_sizes, int n_in,
                              void* d_out, int out_size)
{
    const float* x    = (const float*)d_in[0];
    const int*   mask = (const int*)  d_in[1];
    const float* W0   = (const float*)d_in[2];
    const float* R0   = (const float*)d_in[3];
    const float* b0   = (const float*)d_in[4];
    const float* kg0  = (const float*)d_in[5];
    const float* kb0  = (const float*)d_in[6];
    const float* rg0  = (const float*)d_in[7];
    const float* rb0  = (const float*)d_in[8];
    const float* sg0  = (const float*)d_in[9];
    const float* sb0  = (const float*)d_in[10];
    const float* W1   = (const float*)d_in[11];
    const float* R1   = (const float*)d_in[12];
    const float* b1   = (const float*)d_in[13];
    const float* kg1  = (const float*)d_in[14];
    const float* kb1  = (const float*)d_in[15];
    const float* rg1  = (const float*)d_in[16];
    const float* rb1  = (const float*)d_in[17];
    const float* sg1  = (const float*)d_in[18];
    const float* sb1  = (const float*)d_in[19];
    const float* Wd   = (const float*)d_in[20];
    const float* bd   = (const float*)d_in[21];
    float* out = (float*)d_out;

    float *A0p, *z0p, *z1ap, *z1bp;
    float *xhi, *xlo, *W0hi, *W0lo, *R0hi, *R0lo, *W1hi, *W1lo, *R1hi, *R1lo;
    float *h0shi, *h0slo, *h0ihi, *h0ilo, *h1shi, *h1slo;
    cudaGetSymbolAddress((void**)&A0p,  g_A0);
    cudaGetSymbolAddress((void**)&z0p,  g_z0);
    cudaGetSymbolAddress((void**)&z1ap, g_z1a);
    cudaGetSymbolAddress((void**)&z1bp, g_z1b);
    cudaGetSymbolAddress((void**)&xhi,  g_xhi);
    cudaGetSymbolAddress((void**)&xlo,  g_xlo);
    cudaGetSymbolAddress((void**)&W0hi, g_W0hi);
    cudaGetSymbolAddress((void**)&W0lo, g_W0lo);
    cudaGetSymbolAddress((void**)&R0hi, g_R0hi);
    cudaGetSymbolAddress((void**)&R0lo, g_R0lo);
    cudaGetSymbolAddress((void**)&W1hi, g_W1hi);
    cudaGetSymbolAddress((void**)&W1lo, g_W1lo);
    cudaGetSymbolAddress((void**)&R1hi, g_R1hi);
    cudaGetSymbolAddress((void**)&R1lo, g_R1lo);
    cudaGetSymbolAddress((void**)&h0shi, g_h0s_hi);
    cudaGetSymbolAddress((void**)&h0slo, g_h0s_lo);
    cudaGetSymbolAddress((void**)&h0ihi, g_h0i_hi);
    cudaGetSymbolAddress((void**)&h0ilo, g_h0i_lo);
    cudaGetSymbolAddress((void**)&h1shi, g_h1s_hi);
    cudaGetSymbolAddress((void**)&h1slo, g_h1s_lo);

    cudaFuncSetAttribute(gemm_split, cudaFuncAttributeMaxDynamicSharedMemorySize, SMEM_GEMM);

    // one-time prep
    init_kernel<<<(B * G + 255) / 256, 256>>>();
    split_mat<<<(U * G + 255) / 256, 256>>>(R0, R0hi, R0lo, U * G);
    split_mat<<<(U * G + 255) / 256, 256>>>(W1, W1hi, W1lo, U * G);
    split_mat<<<(U * G + 255) / 256, 256>>>(R1, R1hi, R1lo, U * G);
    split_pad_rows<<<(FP * G + 255) / 256, 256>>>(W0, W0hi, W0lo, F * G, FP * G);
    {
        const size_t n = (size_t)B * T * FP;
        split_pad_cols<<<(unsigned)((n + 255) / 256), 256>>>(x, xhi, xlo, B * T, F, FP);
    }

    // precompute A0 = LN(x @ W0)*kg0 + kb0 + b0
    {
        GArgs a = {};
        a.p[0] = { xhi, xlo, W0hi, W0lo, A0p };
        gemm_split<<<dim3(G / BN, (B * T) / BM, 1), 256, SMEM_GEMM>>>(a, G, FP);
    }
    ln_rows_kernel<<<B * T, 256>>>(kg0, kb0, b0);

    // t = 0 prolog (z0(0) == 0, zeroed in init)
    cell0_kernel<<<B, 256>>>(rg0, rb0, sg0, sb0, mask, 0);

    for (int t = 0; t < T - 1; t++) {
        GArgs a = {};
        a.p[0] = { h0ihi, h0ilo, W1hi, W1lo, z1ap };   // z1a(t)
        a.p[1] = { h1shi, h1slo, R1hi, R1lo, z1bp };   // z1b(t)
        a.p[2] = { h0shi, h0slo, R0hi, R0lo, z0p  };   // z0(t+1)
        gemm_split<<<dim3(G / BN, B / BM, 3), 256, SMEM_GEMM>>>(a, G, U);
        fused_cell_kernel<<<2 * B, 256>>>(rg0, rb0, sg0, sb0,
                                          kg1, kb1, rg1, rb1, sg1, sb1, b1, mask, t);
    }

    // t = T-1 epilog
    {
        GArgs a = {};
        a.p[0] = { h0ihi, h0ilo, W1hi, W1lo, z1ap };
        a.p[1] = { h1shi, h1slo, R1hi, R1lo, z1bp };
        gemm_split<<<dim3(G / BN, B / BM, 2), 256, SMEM_GEMM>>>(a, G, U);
        cell1_kernel<<<B, 256>>>(kg1, kb1, rg1, rb1, sg1, sb1, b1, mask, T - 1);
    }

    dense_kernel<<<B, 256>>>(Wd, bd, out);
}

// round 6
// speedup vs baseline: 1.7546x; 1.7323x over previous
#include <cuda_runtime.h>
#include <cuda_fp16.h>
#include <cstdint>

#define B  1024
#define T  100
#define F  300
#define KP 320     /* F padded to 32-multiple */
#define U  512
#define G  2048    /* 4*U */
#define NC 10
#define EPS 1e-3f

// ---- fp16x3 HMMA GEMM config ----
#define TMC 128
#define TNC 128
#define BKC 32
#define LDAH 40                       /* padded fp16 stride (conflict-free) */
#define TERMB (TMC * LDAH * 2)        /* 10240 B per term tile */
#define STAGEB (4 * TERMB)            /* A0,A1,B0,B1 = 40960 B */
#define SMEM_H (2 * STAGEB)           /* 81920 B */

// ---------------- device scratch ---------------------------------------------------
__device__ __align__(16) float g_A0[(size_t)B * T * G];
__device__ __align__(16) __half g_x0[(size_t)B * T * KP], g_x1[(size_t)B * T * KP];
__device__ __align__(16) __half g_W0a[(size_t)G * KP], g_W0b[(size_t)G * KP];
__device__ __align__(16) __half g_R0a[(size_t)G * U],  g_R0b[(size_t)G * U];
__device__ __align__(16) __half g_W1a[(size_t)G * U],  g_W1b[(size_t)G * U];
__device__ __align__(16) __half g_R1a[(size_t)G * U],  g_R1b[(size_t)G * U];
__device__ __align__(16) float g_z0[B * G], g_z1a[B * G], g_z1b[B * G];
__device__ __align__(16) __half g_h0sa[B * U], g_h0sb[B * U];
__device__ __align__(16) __half g_h0ia[B * U], g_h0ib[B * U];
__device__ __align__(16) __half g_h1sa[B * U], g_h1sb[B * U];
__device__ __align__(16) float g_c0[B * U], g_c1[B * U], g_out[B * U];

__device__ __forceinline__ float sigmf(float x) { return 1.0f / (1.0f + expf(-x)); }

__device__ __forceinline__ void split2(float v, __half& h0, __half& h1)
{
    h0 = __float2half_rn(v);
    h1 = __float2half_rn(v - __half2float(h0));
}

__device__ __forceinline__ void cp16(uint32_t dst, const void* src) {
    asm volatile("cp.async.cg.shared.global [%0], [%1], 16;" :: "r"(dst), "l"(src));
}
__device__ __forceinline__ void cp_commit() { asm volatile("cp.async.commit_group;"); }
__device__ __forceinline__ void cp_wait0()  { asm volatile("cp.async.wait_group 0;"); }

#define MMA16(acc, a, b) \
    asm volatile( \
        "mma.sync.aligned.m16n8k16.row.col.f32.f16.f16.f32 " \
        "{%0,%1,%2,%3},{%4,%5,%6,%7},{%8,%9},{%0,%1,%2,%3};" \
        : "+f"((acc)[0]), "+f"((acc)[1]), "+f"((acc)[2]), "+f"((acc)[3]) \
        : "r"((a)[0]), "r"((a)[1]), "r"((a)[2]), "r"((a)[3]), \
          "r"((b)[0]), "r"((b)[1]))

// ---------------- fp16x3 HMMA GEMM --------------------------------------------------
// C[M,N] = A[M,K] @ Bt[N,K]^T, fp32 emulated as 2 fp16 terms, 3 pair-MMAs.
struct ProbH { const __half *A0, *A1, *B0, *B1; float* C; };
struct GArgsH { ProbH p[3]; };

__global__ __launch_bounds__(256) void gemm_f16x3(GArgsH ga, int N, int K)
{
    extern __shared__ char smem[];
    const uint32_t sb0 = (uint32_t)__cvta_generic_to_shared(smem);

    const ProbH pr = ga.p[blockIdx.z];
    const int tid  = threadIdx.x;
    const int lane = tid & 31;
    const int wid  = tid >> 5;
    const int wm   = wid >> 2;       // 0..1  (64 rows)
    const int wn   = wid & 3;        // 0..3  (32 cols)
    const int m0   = blockIdx.y * TMC;
    const int n0   = blockIdx.x * TNC;
    const int grp  = lane >> 2;      // 0..7
    const int tg   = lane & 3;       // 0..3

    // copy one BK=32 chunk (A terms + B terms) into stage buffer
    auto issue = [&](int stage, int k0) {
        const uint32_t sb = sb0 + (uint32_t)stage * STAGEB;
        const __half* srcs[4] = { pr.A0, pr.A1, pr.B0, pr.B1 };
        const int r0s[4] = { m0, m0, n0, n0 };
#pragma unroll
        for (int t = 0; t < 4; t++) {
#pragma unroll
            for (int i = 0; i < 2; i++) {
                const int idx = tid + i * 256;        // 0..511
                const int r = idx >> 2, gq = idx & 3; // row, 16B granule
                cp16(sb + (uint32_t)(t * TERMB + r * (LDAH * 2) + gq * 16),
                     srcs[t] + (size_t)(r0s[t] + r) * K + k0 + gq * 8);
            }
        }
        cp_commit();
    };

    float acc[4][4][4];
#pragma unroll
    for (int i = 0; i < 4; i++)
#pragma unroll
        for (int j = 0; j < 4; j++)
#pragma unroll
            for (int k = 0; k < 4; k++) acc[i][j][k] = 0.f;

    const int NIT = K / BKC;
    issue(0, 0);

    for (int it = 0; it < NIT; ++it) {
        cp_wait0();
        __syncthreads();
        if (it + 1 < NIT) issue((it + 1) & 1, (it + 1) * BKC);

        const char* sA0 = smem + (it & 1) * STAGEB;
        const char* sA1 = sA0 + TERMB;
        const char* sB0 = sA0 + 2 * TERMB;
        const char* sB1 = sA0 + 3 * TERMB;

#pragma unroll
        for (int kk = 0; kk < 2; kk++) {
            uint32_t a0f[4][4], a1f[4][4], b0f[4][2], b1f[4][2];
#pragma unroll
            for (int im = 0; im < 4; im++) {
                const int base = (wm * 64 + im * 16 + grp) * (LDAH * 2) + kk * 32 + tg * 4;
                a0f[im][0] = *(const uint32_t*)(sA0 + base);
                a0f[im][1] = *(const uint32_t*)(sA0 + base + 8 * (LDAH * 2));
                a0f[im][2] = *(const uint32_t*)(sA0 + base + 16);
                a0f[im][3] = *(const uint32_t*)(sA0 + base + 8 * (LDAH * 2) + 16);
                a1f[im][0] = *(const uint32_t*)(sA1 + base);
                a1f[im][1] = *(const uint32_t*)(sA1 + base + 8 * (LDAH * 2));
                a1f[im][2] = *(const uint32_t*)(sA1 + base + 16);
                a1f[im][3] = *(const uint32_t*)(sA1 + base + 8 * (LDAH * 2) + 16);
            }
#pragma unroll
            for (int jn = 0; jn < 4; jn++) {
                const int base = (wn * 32 + jn * 8 + grp) * (LDAH * 2) + kk * 32 + tg * 4;
                b0f[jn][0] = *(const uint32_t*)(sB0 + base);
                b0f[jn][1] = *(const uint32_t*)(sB0 + base + 16);
                b1f[jn][0] = *(const uint32_t*)(sB1 + base);
                b1f[jn][1] = *(const uint32_t*)(sB1 + base + 16);
            }
#pragma unroll
            for (int im = 0; im < 4; im++)
#pragma unroll
                for (int jn = 0; jn < 4; jn++) {
                    MMA16(acc[im][jn], a1f[im], b0f[jn]);   // lo*hi
                    MMA16(acc[im][jn], a0f[im], b1f[jn]);   // hi*lo
                    MMA16(acc[im][jn], a0f[im], b0f[jn]);   // hi*hi
                }
        }
    }

    // epilogue
#pragma unroll
    for (int im = 0; im < 4; im++) {
        const int row0 = m0 + wm * 64 + im * 16 + grp;
#pragma unroll
        for (int jn = 0; jn < 4; jn++) {
            const int col = n0 + wn * 32 + jn * 8 + tg * 2;
            *(float2*)(pr.C + (size_t)row0 * N + col)       = make_float2(acc[im][jn][0], acc[im][jn][1]);
            *(float2*)(pr.C + (size_t)(row0 + 8) * N + col) = make_float2(acc[im][jn][2], acc[im][jn][3]);
        }
    }
}

// ---------------- one-time prep ------------------------------------------------------
// W[Ksrc,N] fp32 -> 2 fp16 terms, transposed [N,Kd], zero-pad k>=Ksrc
__global__ void wsplit2_t(const float* __restrict__ W, __half* __restrict__ t0,
                          __half* __restrict__ t1, int Kd, int N, int Ksrc)
{
    const size_t i = (size_t)blockIdx.x * 256 + threadIdx.x;
    if (i < (size_t)N * Kd) {
        const int n = (int)(i / Kd), k = (int)(i % Kd);
        const float v = (k < Ksrc) ? W[(size_t)k * N + n] : 0.f;
        __half h0, h1;
        split2(v, h0, h1);
        t0[i] = h0; t1[i] = h1;
    }
}

__global__ void xsplit2(const float* __restrict__ x, __half* __restrict__ t0,
                        __half* __restrict__ t1)
{
    const size_t i = (size_t)blockIdx.x * 256 + threadIdx.x;
    if (i < (size_t)B * T * KP) {
        const size_t r = i / KP;
        const int c = (int)(i % KP);
        const float v = (c < F) ? x[r * F + c] : 0.f;
        __half h0, h1;
        split2(v, h0, h1);
        t0[i] = h0; t1[i] = h1;
    }
}

__global__ void init_kernel()
{
    const size_t i = (size_t)blockIdx.x * 256 + threadIdx.x;
    if (i < (size_t)B * G) g_z0[i] = 0.f;
    if (i < (size_t)B * U) {
        const __half z = __float2half_rn(0.f);
        g_h0sa[i] = z; g_h0sb[i] = z;
        g_h1sa[i] = z; g_h1sb[i] = z;
        g_c0[i] = 0.f; g_c1[i] = 0.f; g_out[i] = 0.f;
    }
}

// ---------------- row LayerNorm on g_A0 ----------------------------------------------
__global__ __launch_bounds__(256) void ln_rows_kernel(const float* __restrict__ gam,
                                                      const float* __restrict__ bet,
                                                      const float* __restrict__ bias)
{
    const size_t r = blockIdx.x;
    float* z = g_A0 + r * (size_t)G;
    const int tid = threadIdx.x, lane = tid & 31, w = tid >> 5;
    __shared__ float sh[2][8];
    __shared__ float bc[2];

    float v[8];
    float s = 0.f, ss = 0.f;
#pragma unroll
    for (int q = 0; q < 8; q++) {
        const float x = z[tid + q * 256];
        v[q] = x; s += x; ss += x * x;
    }
#pragma unroll
    for (int o = 16; o > 0; o >>= 1) {
        s  += __shfl_xor_sync(0xffffffffu, s, o);
        ss += __shfl_xor_sync(0xffffffffu, ss, o);
    }
    if (lane == 0) { sh[0][w] = s; sh[1][w] = ss; }
    __syncthreads();
    if (tid == 0) {
        float S = 0.f, SS = 0.f;
#pragma unroll
        for (int i = 0; i < 8; i++) { S += sh[0][i]; SS += sh[1][i]; }
        const float m = S / (float)G;
        bc[0] = m;
        bc[1] = rsqrtf(SS / (float)G - m * m + EPS);
    }
    __syncthreads();
    const float mean = bc[0], rstd = bc[1];
#pragma unroll
    for (int q = 0; q < 8; q++) {
        const int j = tid + q * 256;
        z[j] = (v[q] - mean) * rstd * gam[j] + bet[j] + bias[j];
    }
}

// ---------------- cell bodies --------------------------------------------------------
__device__ void cell0_body(int b, int t,
                           const float* __restrict__ rg, const float* __restrict__ rb,
                           const float* __restrict__ sg, const float* __restrict__ sb,
                           const int* __restrict__ mask)
{
    const int tid = threadIdx.x, lane = tid & 31, w = tid >> 5;
    const float* z  = g_z0 + (size_t)b * G;
    const float* a0 = g_A0 + (size_t)((size_t)b * T + t) * G;
    __shared__ float sh0[2][8];
    __shared__ float bc0[2];

    float zr[2][4];
    float s = 0.f, ss = 0.f;
#pragma unroll
    for (int q = 0; q < 2; q++) {
        const int u = tid + q * 256;
#pragma unroll
        for (int gg = 0; gg < 4; gg++) {
            const float v = z[gg * U + u];
            zr[q][gg] = v; s += v; ss += v * v;
        }
    }
#pragma unroll
    for (int o = 16; o > 0; o >>= 1) {
        s  += __shfl_xor_sync(0xffffffffu, s, o);
        ss += __shfl_xor_sync(0xffffffffu, ss, o);
    }
    if (lane == 0) { sh0[0][w] = s; sh0[1][w] = ss; }
    __syncthreads();
    if (tid == 0) {
        float S = 0.f, SS = 0.f;
#pragma unroll
        for (int i = 0; i < 8; i++) { S += sh0[0][i]; SS += sh0[1][i]; }
        const float m = S / (float)G;
        bc0[0] = m;
        bc0[1] = rsqrtf(SS / (float)G - m * m + EPS);
    }
    __syncthreads();
    const float mean = bc0[0], rstd = bc0[1];

    float cn[2], zo[2];
    float s2 = 0.f, q2 = 0.f;
#pragma unroll
    for (int q = 0; q < 2; q++) {
        const int u = tid + q * 256;
        const float zi = (zr[q][0] - mean) * rstd * rg[u        ] + rb[u        ] + a0[u        ];
        const float zf = (zr[q][1] - mean) * rstd * rg[U     + u] + rb[U     + u] + a0[U     + u];
        const float zg = (zr[q][2] - mean) * rstd * rg[2 * U + u] + rb[2 * U + u] + a0[2 * U + u];
        zo[q]          = (zr[q][3] - mean) * rstd * rg[3 * U + u] + rb[3 * U + u] + a0[3 * U + u];
        const float c = g_c0[(size_t)b * U + u];
        const float v = sigmf(zf) * c + sigmf(zi) * tanhf(zg);
        cn[q] = v; s2 += v; q2 += v * v;
    }
#pragma unroll
    for (int o = 16; o > 0; o >>= 1) {
        s2 += __shfl_xor_sync(0xffffffffu, s2, o);
        q2 += __shfl_xor_sync(0xffffffffu, q2, o);
    }
    __syncthreads();
    if (lane == 0) { sh0[0][w] = s2; sh0[1][w] = q2; }
    __syncthreads();
    if (tid == 0) {
        float S = 0.f, P = 0.f;
#pragma unroll
        for (int i = 0; i < 8; i++) { S += sh0[0][i]; P += sh0[1][i]; }
        const float m = S / (float)U;
        bc0[0] = m;
        bc0[1] = rsqrtf(P / (float)U - m * m + EPS);
    }
    __syncthreads();
    const float m2 = bc0[0], r2 = bc0[1];
    const int msk = mask[b * T + t];
#pragma unroll
    for (int q = 0; q < 2; q++) {
        const int u = tid + q * 256;
        const float cl = (cn[q] - m2) * r2 * sg[u] + sb[u];
        const float hn = sigmf(zo[q]) * tanhf(cl);
        __half h0, h1;
        split2(hn, h0, h1);
        g_h0ia[(size_t)b * U + u] = h0;
        g_h0ib[(size_t)b * U + u] = h1;
        if (msk) {
            g_h0sa[(size_t)b * U + u] = h0;
            g_h0sb[(size_t)b * U + u] = h1;
            g_c0  [(size_t)b * U + u] = cl;
        }
    }
}

__device__ void cell1_body(int b, int t,
                           const float* __restrict__ kg, const float* __restrict__ kb,
                           const float* __restrict__ rg, const float* __restrict__ rb,
                           const float* __restrict__ sg, const float* __restrict__ sb,
                           const float* __restrict__ bias, const int* __restrict__ mask)
{
    const int tid = threadIdx.x, lane = tid & 31, w = tid >> 5;
    const float* za = g_z1a + (size_t)b * G;
    const float* zb = g_z1b + (size_t)b * G;
    __shared__ float sh1[4][8];
    __shared__ float bc1[4];

    float va[2][4], vb[2][4];
    float s1 = 0.f, p1 = 0.f, s2 = 0.f, p2 = 0.f;
#pragma unroll
    for (int q = 0; q < 2; q++) {
        const int u = tid + q * 256;
#pragma unroll
        for (int gg = 0; gg < 4; gg++) {
            const float x1 = za[gg * U + u];
            const float x2 = zb[gg * U + u];
            va[q][gg] = x1; vb[q][gg] = x2;
            s1 += x1; p1 += x1 * x1; s2 += x2; p2 += x2 * x2;
        }
    }
#pragma unroll
    for (int o = 16; o > 0; o >>= 1) {
        s1 += __shfl_xor_sync(0xffffffffu, s1, o);
        p1 += __shfl_xor_sync(0xffffffffu, p1, o);
        s2 += __shfl_xor_sync(0xffffffffu, s2, o);
        p2 += __shfl_xor_sync(0xffffffffu, p2, o);
    }
    if (lane == 0) { sh1[0][w] = s1; sh1[1][w] = p1; sh1[2][w] = s2; sh1[3][w] = p2; }
    __syncthreads();
    if (tid == 0) {
        float S1 = 0.f, P1 = 0.f, S2 = 0.f, P2 = 0.f;
#pragma unroll
        for (int i = 0; i < 8; i++) { S1 += sh1[0][i]; P1 += sh1[1][i]; S2 += sh1[2][i]; P2 += sh1[3][i]; }
        const float m1 = S1 / (float)G, m2 = S2 / (float)G;
        bc1[0] = m1; bc1[1] = rsqrtf(P1 / (float)G - m1 * m1 + EPS);
        bc1[2] = m2; bc1[3] = rsqrtf(P2 / (float)G - m2 * m2 + EPS);
    }
    __syncthreads();
    const float m1 = bc1[0], r1 = bc1[1], m2 = bc1[2], r2 = bc1[3];

    float cn[2], zo[2];
    float s3 = 0.f, p3 = 0.f;
#pragma unroll
    for (int q = 0; q < 2; q++) {
        const int u = tid + q * 256;
        float zg4[4];
#pragma unroll
        for (int gg = 0; gg < 4; gg++) {
            const int j = gg * U + u;
            zg4[gg] = (va[q][gg] - m1) * r1 * kg[j] + kb[j]
                    + (vb[q][gg] - m2) * r2 * rg[j] + rb[j] + bias[j];
        }
        const float c = g_c1[(size_t)b * U + u];
        const float v = sigmf(zg4[1]) * c + sigmf(zg4[0]) * tanhf(zg4[2]);
        cn[q] = v; zo[q] = zg4[3]; s3 += v; p3 += v * v;
    }
#pragma unroll
    for (int o = 16; o > 0; o >>= 1) {
        s3 += __shfl_xor_sync(0xffffffffu, s3, o);
        p3 += __shfl_xor_sync(0xffffffffu, p3, o);
    }
    __syncthreads();
    if (lane == 0) { sh1[0][w] = s3; sh1[1][w] = p3; }
    __syncthreads();
    if (tid == 0) {
        float S = 0.f, P = 0.f;
#pragma unroll
        for (int i = 0; i < 8; i++) { S += sh1[0][i]; P += sh1[1][i]; }
        const float m = S / (float)U;
        bc1[0] = m;
        bc1[1] = rsqrtf(P / (float)U - m * m + EPS);
    }
    __syncthreads();
    const float mc = bc1[0], rc = bc1[1];
    const int msk = mask[b * T + t];
#pragma unroll
    for (int q = 0; q < 2; q++) {
        const int u = tid + q * 256;
        const float cl = (cn[q] - mc) * rc * sg[u] + sb[u];
        const float hn = sigmf(zo[q]) * tanhf(cl);
        if (msk) {
            __half h0, h1;
            split2(hn, h0, h1);
            g_h1sa[(size_t)b * U + u] = h0;
            g_h1sb[(size_t)b * U + u] = h1;
            g_c1 [(size_t)b * U + u] = cl;
            g_out[(size_t)b * U + u] = hn;
        }
    }
}

__global__ __launch_bounds__(256) void cell0_kernel(const float* rg, const float* rb,
                                                    const float* sg, const float* sb,
                                                    const int* mask, int t)
{
    cell0_body(blockIdx.x, t, rg, rb, sg, sb, mask);
}

__global__ __launch_bounds__(256) void cell1_kernel(const float* kg, const float* kb,
                                                    const float* rg, const float* rb,
                                                    const float* sg, const float* sb,
                                                    const float* bias, const int* mask, int t)
{
    cell1_body(blockIdx.x, t, kg, kb, rg, rb, sg, sb, bias, mask);
}

// fused: blocks [0,B) do cell1(t); blocks [B,2B) do cell0(t+1)
__global__ __launch_bounds__(256) void fused_cell_kernel(
    const float* rg0, const float* rb0, const float* sg0, const float* sb0,
    const float* kg1, const float* kb1, const float* rg1, const float* rb1,
    const float* sg1, const float* sb1, const float* b1,
    const int* mask, int t)
{
    if (blockIdx.x < B)
        cell1_body(blockIdx.x, t, kg1, kb1, rg1, rb1, sg1, sb1, b1, mask);
    else
        cell0_body(blockIdx.x - B, t + 1, rg0, rb0, sg0, sb0, mask);
}

// ---------------- dense + softmax -----------------------------------------------------
__global__ __launch_bounds__(256) void dense_kernel(const float* __restrict__ Wd,
                                                    const float* __restrict__ bd,
                                                    float* __restrict__ out)
{
    const int b = blockIdx.x, tid = threadIdx.x, lane = tid & 31, w = tid >> 5;
    float p[NC];
#pragma unroll
    for (int c = 0; c < NC; c++) p[c] = 0.f;
    for (int u = tid; u < U; u += 256) {
        const float h = g_out[(size_t)b * U + u];
#pragma unroll
        for (int c = 0; c < NC; c++) p[c] += h * Wd[u * NC + c];
    }
    __shared__ float sh[NC][8];
#pragma unroll
    for (int c = 0; c < NC; c++) {
        float v = p[c];
#pragma unroll
        for (int o = 16; o > 0; o >>= 1) v += __shfl_xor_sync(0xffffffffu, v, o);
        if (lane == 0) sh[c][w] = v;
    }
    __syncthreads();
    if (tid == 0) {
        float lg[NC];
        float mx = -1e30f;
#pragma unroll
        for (int c = 0; c < NC; c++) {
            float l = bd[c];
#pragma unroll
            for (int i = 0; i < 8; i++) l += sh[c][i];
            lg[c] = l;
            mx = fmaxf(mx, l);
        }
        float sum = 0.f;
#pragma unroll
        for (int c = 0; c < NC; c++) { lg[c] = expf(lg[c] - mx); sum += lg[c]; }
        const float inv = 1.f / sum;
#pragma unroll
        for (int c = 0; c < NC; c++) out[b * NC + c] = lg[c] * inv;
    }
}

// ---------------- launch ---------------------------------------------------------------
extern "C" void kernel_launch(void* const* d_in, const int* in_sizes, int n_in,
                              void* d_out, int out_size)
{
    const float* x    = (const float*)d_in[0];
    const int*   mask = (const int*)  d_in[1];
    const float* W0   = (const float*)d_in[2];
    const float* R0   = (const float*)d_in[3];
    const float* b0   = (const float*)d_in[4];
    const float* kg0  = (const float*)d_in[5];
    const float* kb0  = (const float*)d_in[6];
    const float* rg0  = (const float*)d_in[7];
    const float* rb0  = (const float*)d_in[8];
    const float* sg0  = (const float*)d_in[9];
    const float* sb0  = (const float*)d_in[10];
    const float* W1   = (const float*)d_in[11];
    const float* R1   = (const float*)d_in[12];
    const float* b1   = (const float*)d_in[13];
    const float* kg1  = (const float*)d_in[14];
    const float* kb1  = (const float*)d_in[15];
    const float* rg1  = (const float*)d_in[16];
    const float* rb1  = (const float*)d_in[17];
    const float* sg1  = (const float*)d_in[18];
    const float* sb1  = (const float*)d_in[19];
    const float* Wd   = (const float*)d_in[20];
    const float* bd   = (const float*)d_in[21];
    float* out = (float*)d_out;

    float *A0p, *z0p, *z1ap, *z1bp;
    __half *x0, *x1, *W0a, *W0b, *R0a, *R0b, *W1a, *W1b, *R1a, *R1b;
    __half *h0sa, *h0sb, *h0ia, *h0ib, *h1sa, *h1sb;
    cudaGetSymbolAddress((void**)&A0p,  g_A0);
    cudaGetSymbolAddress((void**)&z0p,  g_z0);
    cudaGetSymbolAddress((void**)&z1ap, g_z1a);
    cudaGetSymbolAddress((void**)&z1bp, g_z1b);
    cudaGetSymbolAddress((void**)&x0,   g_x0);
    cudaGetSymbolAddress((void**)&x1,   g_x1);
    cudaGetSymbolAddress((void**)&W0a,  g_W0a);
    cudaGetSymbolAddress((void**)&W0b,  g_W0b);
    cudaGetSymbolAddress((void**)&R0a,  g_R0a);
    cudaGetSymbolAddress((void**)&R0b,  g_R0b);
    cudaGetSymbolAddress((void**)&W1a,  g_W1a);
    cudaGetSymbolAddress((void**)&W1b,  g_W1b);
    cudaGetSymbolAddress((void**)&R1a,  g_R1a);
    cudaGetSymbolAddress((void**)&R1b,  g_R1b);
    cudaGetSymbolAddress((void**)&h0sa, g_h0sa);
    cudaGetSymbolAddress((void**)&h0sb, g_h0sb);
    cudaGetSymbolAddress((void**)&h0ia, g_h0ia);
    cudaGetSymbolAddress((void**)&h0ib, g_h0ib);
    cudaGetSymbolAddress((void**)&h1sa, g_h1sa);
    cudaGetSymbolAddress((void**)&h1sb, g_h1sb);

    cudaFuncSetAttribute(gemm_f16x3, cudaFuncAttributeMaxDynamicSharedMemorySize, SMEM_H);

    // one-time prep
    const size_t nW0 = (size_t)G * KP;
    const size_t nRW = (size_t)G * U;
    const size_t nXT = (size_t)B * T * KP;
    init_kernel<<<(B * G + 255) / 256, 256>>>();
    wsplit2_t<<<(unsigned)((nW0 + 255) / 256), 256>>>(W0, W0a, W0b, KP, G, F);
    wsplit2_t<<<(unsigned)((nRW + 255) / 256), 256>>>(R0, R0a, R0b, U, G, U);
    wsplit2_t<<<(unsigned)((nRW + 255) / 256), 256>>>(W1, W1a, W1b, U, G, U);
    wsplit2_t<<<(unsigned)((nRW + 255) / 256), 256>>>(R1, R1a, R1b, U, G, U);
    xsplit2<<<(unsigned)((nXT + 255) / 256), 256>>>(x, x0, x1);

    // precompute A0 = LN(x @ W0)*kg0 + kb0 + b0
    {
        GArgsH a = {};
        a.p[0] = { x0, x1, W0a, W0b, A0p };
        gemm_f16x3<<<dim3(G / TNC, (B * T) / TMC, 1), 256, SMEM_H>>>(a, G, KP);
    }
    ln_rows_kernel<<<B * T, 256>>>(kg0, kb0, b0);

    // t = 0 prolog (z0(0) == 0)
    cell0_kernel<<<B, 256>>>(rg0, rb0, sg0, sb0, mask, 0);

    for (int t = 0; t < T - 1; t++) {
        GArgsH a = {};
        a.p[0] = { h0ia, h0ib, W1a, W1b, z1ap };   // z1a(t)
        a.p[1] = { h1sa, h1sb, R1a, R1b, z1bp };   // z1b(t)
        a.p[2] = { h0sa, h0sb, R0a, R0b, z0p  };   // z0(t+1)
        gemm_f16x3<<<dim3(G / TNC, B / TMC, 3), 256, SMEM_H>>>(a, G, U);
        fused_cell_kernel<<<2 * B, 256>>>(rg0, rb0, sg0, sb0,
                                          kg1, kb1, rg1, rb1, sg1, sb1, b1, mask, t);
    }

    // t = T-1 epilog
    {
        GArgsH a = {};
        a.p[0] = { h0ia, h0ib, W1a, W1b, z1ap };
        a.p[1] = { h1sa, h1sb, R1a, R1b, z1bp };
        gemm_f16x3<<<dim3(G / TNC, B / TMC, 2), 256, SMEM_H>>>(a, G, U);
        cell1_kernel<<<B, 256>>>(kg1, kb1, rg1, rb1, sg1, sb1, b1, mask, T - 1);
    }

    dense_kernel<<<B, 256>>>(Wd, bd, out);
}

// round 7
// speedup vs baseline: 2.0627x; 1.1756x over previous
#include <cuda_runtime.h>
#include <cuda_fp16.h>
#include <cstdint>

#define B  1024
#define T  100
#define F  300
#define KP 320     /* F padded to 32-multiple */
#define U  512
#define G  2048    /* 4*U */
#define NC 10
#define EPS 1e-3f

// ---- fp16x3 HMMA GEMM config ----
#define TMC 128
#define TNC 128
#define BKC 32
#define LDAH 40                       /* padded fp16 stride (conflict-free) */
#define ROWB (LDAH * 2)               /* 80 B row stride */
#define TERMB (TMC * ROWB)            /* 10240 B per term tile */
#define STAGEB (4 * TERMB)            /* A0,A1,B0,B1 = 40960 B */
#define SMEM_H (2 * STAGEB)           /* 81920 B */

// ---------------- device scratch ---------------------------------------------------
__device__ __align__(16) float g_A0[(size_t)B * T * G];
__device__ __align__(16) __half g_x0[(size_t)B * T * KP], g_x1[(size_t)B * T * KP];
__device__ __align__(16) __half g_W0a[(size_t)G * KP], g_W0b[(size_t)G * KP];
__device__ __align__(16) __half g_R0a[(size_t)G * U],  g_R0b[(size_t)G * U];
__device__ __align__(16) __half g_W1a[(size_t)G * U],  g_W1b[(size_t)G * U];
__device__ __align__(16) __half g_R1a[(size_t)G * U],  g_R1b[(size_t)G * U];
__device__ __align__(16) float g_z0[B * G], g_z1a[B * G], g_z1b[B * G];
__device__ __align__(16) __half g_h0sa[B * U], g_h0sb[B * U];
__device__ __align__(16) __half g_h0ia[B * U], g_h0ib[B * U];
__device__ __align__(16) __half g_h1sa[B * U], g_h1sb[B * U];
__device__ __align__(16) float g_c0[B * U], g_c1[B * U], g_out[B * U];

__device__ __forceinline__ float sigmf(float x) { return 1.0f / (1.0f + expf(-x)); }

__device__ __forceinline__ void split2(float v, __half& h0, __half& h1)
{
    h0 = __float2half_rn(v);
    h1 = __float2half_rn(v - __half2float(h0));
}

__device__ __forceinline__ void cp16(uint32_t dst, const void* src) {
    asm volatile("cp.async.cg.shared.global [%0], [%1], 16;" :: "r"(dst), "l"(src));
}
__device__ __forceinline__ void cp_commit() { asm volatile("cp.async.commit_group;"); }
__device__ __forceinline__ void cp_wait0()  { asm volatile("cp.async.wait_group 0;"); }

#define MMA16(acc, a, b) \
    asm volatile( \
        "mma.sync.aligned.m16n8k16.row.col.f32.f16.f16.f32 " \
        "{%0,%1,%2,%3},{%4,%5,%6,%7},{%8,%9},{%0,%1,%2,%3};" \
        : "+f"((acc)[0]), "+f"((acc)[1]), "+f"((acc)[2]), "+f"((acc)[3]) \
        : "r"((a)[0]), "r"((a)[1]), "r"((a)[2]), "r"((a)[3]), \
          "r"((b)[0]), "r"((b)[1]))

#define LDSM4(r, addr) \
    asm volatile("ldmatrix.sync.aligned.m8n8.x4.shared.b16 {%0,%1,%2,%3}, [%4];" \
        : "=r"((r)[0]), "=r"((r)[1]), "=r"((r)[2]), "=r"((r)[3]) : "r"(addr))

// ---------------- fp16x3 HMMA GEMM --------------------------------------------------
// C[M,N] = A[M,K] @ Bt[N,K]^T, fp32 emulated as 2 fp16 terms, 3 pair-MMAs.
struct ProbH { const __half *A0, *A1, *B0, *B1; float* C; };
struct GArgsH { ProbH p[3]; };

__global__ __launch_bounds__(256, 2) void gemm_f16x3(GArgsH ga, int N, int K)
{
    extern __shared__ char smem[];
    const uint32_t sb0 = (uint32_t)__cvta_generic_to_shared(smem);

    const ProbH pr = ga.p[blockIdx.z];
    const int tid  = threadIdx.x;
    const int lane = tid & 31;
    const int wid  = tid >> 5;
    const int wm   = wid >> 2;       // 0..1  (64 rows)
    const int wn   = wid & 3;        // 0..3  (32 cols)
    const int m0   = blockIdx.y * TMC;
    const int n0   = blockIdx.x * TNC;
    const int grp  = lane >> 2;      // 0..7
    const int tg   = lane & 3;       // 0..3

    // per-lane ldmatrix offsets (x4 tile decomposition)
    const int lm = lane >> 3, lr = lane & 7;
    const uint32_t aoff = (uint32_t)((((lm & 1) * 8) + lr) * ROWB + (lm >> 1) * 16);
    const uint32_t boff = (uint32_t)((((lm >> 1) * 8) + lr) * ROWB + (lm & 1) * 16);

    // copy one BK=32 chunk (A terms + B terms) into stage buffer
    auto issue = [&](int stage, int k0) {
        const uint32_t sb = sb0 + (uint32_t)stage * STAGEB;
        const __half* srcs[4] = { pr.A0, pr.A1, pr.B0, pr.B1 };
        const int r0s[4] = { m0, m0, n0, n0 };
#pragma unroll
        for (int t = 0; t < 4; t++) {
#pragma unroll
            for (int i = 0; i < 2; i++) {
                const int idx = tid + i * 256;        // 0..511
                const int r = idx >> 2, gq = idx & 3; // row, 16B granule
                cp16(sb + (uint32_t)(t * TERMB + r * ROWB + gq * 16),
                     srcs[t] + (size_t)(r0s[t] + r) * K + k0 + gq * 8);
            }
        }
        cp_commit();
    };

    float acc[4][4][4];
#pragma unroll
    for (int i = 0; i < 4; i++)
#pragma unroll
        for (int j = 0; j < 4; j++)
#pragma unroll
            for (int k = 0; k < 4; k++) acc[i][j][k] = 0.f;

    const int NIT = K / BKC;
    issue(0, 0);

    for (int it = 0; it < NIT; ++it) {
        cp_wait0();
        __syncthreads();
        if (it + 1 < NIT) issue((it + 1) & 1, (it + 1) * BKC);

        const uint32_t sst = sb0 + (uint32_t)(it & 1) * STAGEB;
        const uint32_t aBase = sst + (uint32_t)((wm * 64) * ROWB) + aoff;
        const uint32_t bBase = sst + 2 * TERMB + (uint32_t)((wn * 32) * ROWB) + boff;

#pragma unroll
        for (int kk = 0; kk < 2; kk++) {
            uint32_t a0f[4][4], a1f[4][4], b0t[2][4], b1t[2][4];
#pragma unroll
            for (int im = 0; im < 4; im++) {
                const uint32_t ab = aBase + (uint32_t)(im * 16 * ROWB + kk * 32);
                LDSM4(a0f[im], ab);
                LDSM4(a1f[im], ab + TERMB);
            }
#pragma unroll
            for (int jp = 0; jp < 2; jp++) {
                const uint32_t bb = bBase + (uint32_t)(jp * 16 * ROWB + kk * 32);
                LDSM4(b0t[jp], bb);
                LDSM4(b1t[jp], bb + TERMB);
            }
#pragma unroll
            for (int im = 0; im < 4; im++)
#pragma unroll
                for (int jn = 0; jn < 4; jn++) {
                    const uint32_t* b0p = &b0t[jn >> 1][(jn & 1) * 2];
                    const uint32_t* b1p = &b1t[jn >> 1][(jn & 1) * 2];
                    MMA16(acc[im][jn], a1f[im], b0p);   // lo*hi
                    MMA16(acc[im][jn], a0f[im], b1p);   // hi*lo
                    MMA16(acc[im][jn], a0f[im], b0p);   // hi*hi
                }
        }
    }

    // epilogue
#pragma unroll
    for (int im = 0; im < 4; im++) {
        const int row0 = m0 + wm * 64 + im * 16 + grp;
#pragma unroll
        for (int jn = 0; jn < 4; jn++) {
            const int col = n0 + wn * 32 + jn * 8 + tg * 2;
            *(float2*)(pr.C + (size_t)row0 * N + col)       = make_float2(acc[im][jn][0], acc[im][jn][1]);
            *(float2*)(pr.C + (size_t)(row0 + 8) * N + col) = make_float2(acc[im][jn][2], acc[im][jn][3]);
        }
    }
}

// ---------------- one-time prep ------------------------------------------------------
// W[Ksrc,N] fp32 -> 2 fp16 terms, transposed [N,Kd], zero-pad k>=Ksrc
__global__ void wsplit2_t(const float* __restrict__ W, __half* __restrict__ t0,
                          __half* __restrict__ t1, int Kd, int N, int Ksrc)
{
    const size_t i = (size_t)blockIdx.x * 256 + threadIdx.x;
    if (i < (size_t)N * Kd) {
        const int n = (int)(i / Kd), k = (int)(i % Kd);
        const float v = (k < Ksrc) ? W[(size_t)k * N + n] : 0.f;
        __half h0, h1;
        split2(v, h0, h1);
        t0[i] = h0; t1[i] = h1;
    }
}

__global__ void xsplit2(const float* __restrict__ x, __half* __restrict__ t0,
                        __half* __restrict__ t1)
{
    const size_t i = (size_t)blockIdx.x * 256 + threadIdx.x;
    if (i < (size_t)B * T * KP) {
        const size_t r = i / KP;
        const int c = (int)(i % KP);
        const float v = (c < F) ? x[r * F + c] : 0.f;
        __half h0, h1;
        split2(v, h0, h1);
        t0[i] = h0; t1[i] = h1;
    }
}

__global__ void init_kernel()
{
    const size_t i = (size_t)blockIdx.x * 256 + threadIdx.x;
    if (i < (size_t)B * G) g_z0[i] = 0.f;
    if (i < (size_t)B * U) {
        const __half z = __float2half_rn(0.f);
        g_h0sa[i] = z; g_h0sb[i] = z;
        g_h1sa[i] = z; g_h1sb[i] = z;
        g_c0[i] = 0.f; g_c1[i] = 0.f; g_out[i] = 0.f;
    }
}

// ---------------- row LayerNorm on g_A0 ----------------------------------------------
__global__ __launch_bounds__(256) void ln_rows_kernel(const float* __restrict__ gam,
                                                      const float* __restrict__ bet,
                                                      const float* __restrict__ bias)
{
    const size_t r = blockIdx.x;
    float* z = g_A0 + r * (size_t)G;
    const int tid = threadIdx.x, lane = tid & 31, w = tid >> 5;
    __shared__ float sh[2][8];
    __shared__ float bc[2];

    float v[8];
    float s = 0.f, ss = 0.f;
#pragma unroll
    for (int q = 0; q < 8; q++) {
        const float x = z[tid + q * 256];
        v[q] = x; s += x; ss += x * x;
    }
#pragma unroll
    for (int o = 16; o > 0; o >>= 1) {
        s  += __shfl_xor_sync(0xffffffffu, s, o);
        ss += __shfl_xor_sync(0xffffffffu, ss, o);
    }
    if (lane == 0) { sh[0][w] = s; sh[1][w] = ss; }
    __syncthreads();
    if (tid == 0) {
        float S = 0.f, SS = 0.f;
#pragma unroll
        for (int i = 0; i < 8; i++) { S += sh[0][i]; SS += sh[1][i]; }
        const float m = S / (float)G;
        bc[0] = m;
        bc[1] = rsqrtf(SS / (float)G - m * m + EPS);
    }
    __syncthreads();
    const float mean = bc[0], rstd = bc[1];
#pragma unroll
    for (int q = 0; q < 8; q++) {
        const int j = tid + q * 256;
        z[j] = (v[q] - mean) * rstd * gam[j] + bet[j] + bias[j];
    }
}

// ---------------- cell bodies --------------------------------------------------------
__device__ void cell0_body(int b, int t,
                           const float* __restrict__ rg, const float* __restrict__ rb,
                           const float* __restrict__ sg, const float* __restrict__ sb,
                           const int* __restrict__ mask)
{
    const int tid = threadIdx.x, lane = tid & 31, w = tid >> 5;
    const float* z  = g_z0 + (size_t)b * G;
    const float* a0 = g_A0 + (size_t)((size_t)b * T + t) * G;
    __shared__ float sh0[2][8];
    __shared__ float bc0[2];

    float zr[2][4];
    float s = 0.f, ss = 0.f;
#pragma unroll
    for (int q = 0; q < 2; q++) {
        const int u = tid + q * 256;
#pragma unroll
        for (int gg = 0; gg < 4; gg++) {
            const float v = z[gg * U + u];
            zr[q][gg] = v; s += v; ss += v * v;
        }
    }
#pragma unroll
    for (int o = 16; o > 0; o >>= 1) {
        s  += __shfl_xor_sync(0xffffffffu, s, o);
        ss += __shfl_xor_sync(0xffffffffu, ss, o);
    }
    if (lane == 0) { sh0[0][w] = s; sh0[1][w] = ss; }
    __syncthreads();
    if (tid == 0) {
        float S = 0.f, SS = 0.f;
#pragma unroll
        for (int i = 0; i < 8; i++) { S += sh0[0][i]; SS += sh0[1][i]; }
        const float m = S / (float)G;
        bc0[0] = m;
        bc0[1] = rsqrtf(SS / (float)G - m * m + EPS);
    }
    __syncthreads();
    const float mean = bc0[0], rstd = bc0[1];

    float cn[2], zo[2];
    float s2 = 0.f, q2 = 0.f;
#pragma unroll
    for (int q = 0; q < 2; q++) {
        const int u = tid + q * 256;
        const float zi = (zr[q][0] - mean) * rstd * rg[u        ] + rb[u        ] + a0[u        ];
        const float zf = (zr[q][1] - mean) * rstd * rg[U     + u] + rb[U     + u] + a0[U     + u];
        const float zg = (zr[q][2] - mean) * rstd * rg[2 * U + u] + rb[2 * U + u] + a0[2 * U + u];
        zo[q]          = (zr[q][3] - mean) * rstd * rg[3 * U + u] + rb[3 * U + u] + a0[3 * U + u];
        const float c = g_c0[(size_t)b * U + u];
        const float v = sigmf(zf) * c + sigmf(zi) * tanhf(zg);
        cn[q] = v; s2 += v; q2 += v * v;
    }
#pragma unroll
    for (int o = 16; o > 0; o >>= 1) {
        s2 += __shfl_xor_sync(0xffffffffu, s2, o);
        q2 += __shfl_xor_sync(0xffffffffu, q2, o);
    }
    __syncthreads();
    if (lane == 0) { sh0[0][w] = s2; sh0[1][w] = q2; }
    __syncthreads();
    if (tid == 0) {
        float S = 0.f, P = 0.f;
#pragma unroll
        for (int i = 0; i < 8; i++) { S += sh0[0][i]; P += sh0[1][i]; }
        const float m = S / (float)U;
        bc0[0] = m;
        bc0[1] = rsqrtf(P / (float)U - m * m + EPS);
    }
    __syncthreads();
    const float m2 = bc0[0], r2 = bc0[1];
    const int msk = mask[b * T + t];
#pragma unroll
    for (int q = 0; q < 2; q++) {
        const int u = tid + q * 256;
        const float cl = (cn[q] - m2) * r2 * sg[u] + sb[u];
        const float hn = sigmf(zo[q]) * tanhf(cl);
        __half h0, h1;
        split2(hn, h0, h1);
        g_h0ia[(size_t)b * U + u] = h0;
        g_h0ib[(size_t)b * U + u] = h1;
        if (msk) {
            g_h0sa[(size_t)b * U + u] = h0;
            g_h0sb[(size_t)b * U + u] = h1;
            g_c0  [(size_t)b * U + u] = cl;
        }
    }
}

__device__ void cell1_body(int b, int t,
                           const float* __restrict__ kg, const float* __restrict__ kb,
                           const float* __restrict__ rg, const float* __restrict__ rb,
                           const float* __restrict__ sg, const float* __restrict__ sb,
                           const float* __restrict__ bias, const int* __restrict__ mask)
{
    const int tid = threadIdx.x, lane = tid & 31, w = tid >> 5;
    const float* za = g_z1a + (size_t)b * G;
    const float* zb = g_z1b + (size_t)b * G;
    __shared__ float sh1[4][8];
    __shared__ float bc1[4];

    float va[2][4], vb[2][4];
    float s1 = 0.f, p1 = 0.f, s2 = 0.f, p2 = 0.f;
#pragma unroll
    for (int q = 0; q < 2; q++) {
        const int u = tid + q * 256;
#pragma unroll
        for (int gg = 0; gg < 4; gg++) {
            const float x1 = za[gg * U + u];
            const float x2 = zb[gg * U + u];
            va[q][gg] = x1; vb[q][gg] = x2;
            s1 += x1; p1 += x1 * x1; s2 += x2; p2 += x2 * x2;
        }
    }
#pragma unroll
    for (int o = 16; o > 0; o >>= 1) {
        s1 += __shfl_xor_sync(0xffffffffu, s1, o);
        p1 += __shfl_xor_sync(0xffffffffu, p1, o);
        s2 += __shfl_xor_sync(0xffffffffu, s2, o);
        p2 += __shfl_xor_sync(0xffffffffu, p2, o);
    }
    if (lane == 0) { sh1[0][w] = s1; sh1[1][w] = p1; sh1[2][w] = s2; sh1[3][w] = p2; }
    __syncthreads();
    if (tid == 0) {
        float S1 = 0.f, P1 = 0.f, S2 = 0.f, P2 = 0.f;
#pragma unroll
        for (int i = 0; i < 8; i++) { S1 += sh1[0][i]; P1 += sh1[1][i]; S2 += sh1[2][i]; P2 += sh1[3][i]; }
        const float m1 = S1 / (float)G, m2 = S2 / (float)G;
        bc1[0] = m1; bc1[1] = rsqrtf(P1 / (float)G - m1 * m1 + EPS);
        bc1[2] = m2; bc1[3] = rsqrtf(P2 / (float)G - m2 * m2 + EPS);
    }
    __syncthreads();
    const float m1 = bc1[0], r1 = bc1[1], m2 = bc1[2], r2 = bc1[3];

    float cn[2], zo[2];
    float s3 = 0.f, p3 = 0.f;
#pragma unroll
    for (int q = 0; q < 2; q++) {
        const int u = tid + q * 256;
        float zg4[4];
#pragma unroll
        for (int gg = 0; gg < 4; gg++) {
            const int j = gg * U + u;
            zg4[gg] = (va[q][gg] - m1) * r1 * kg[j] + kb[j]
                    + (vb[q][gg] - m2) * r2 * rg[j] + rb[j] + bias[j];
        }
        const float c = g_c1[(size_t)b * U + u];
        const float v = sigmf(zg4[1]) * c + sigmf(zg4[0]) * tanhf(zg4[2]);
        cn[q] = v; zo[q] = zg4[3]; s3 += v; p3 += v * v;
    }
#pragma unroll
    for (int o = 16; o > 0; o >>= 1) {
        s3 += __shfl_xor_sync(0xffffffffu, s3, o);
        p3 += __shfl_xor_sync(0xffffffffu, p3, o);
    }
    __syncthreads();
    if (lane == 0) { sh1[0][w] = s3; sh1[1][w] = p3; }
    __syncthreads();
    if (tid == 0) {
        float S = 0.f, P = 0.f;
#pragma unroll
        for (int i = 0; i < 8; i++) { S += sh1[0][i]; P += sh1[1][i]; }
        const float m = S / (float)U;
        bc1[0] = m;
        bc1[1] = rsqrtf(P / (float)U - m * m + EPS);
    }
    __syncthreads();
    const float mc = bc1[0], rc = bc1[1];
    const int msk = mask[b * T + t];
#pragma unroll
    for (int q = 0; q < 2; q++) {
        const int u = tid + q * 256;
        const float cl = (cn[q] - mc) * rc * sg[u] + sb[u];
        const float hn = sigmf(zo[q]) * tanhf(cl);
        if (msk) {
            __half h0, h1;
            split2(hn, h0, h1);
            g_h1sa[(size_t)b * U + u] = h0;
            g_h1sb[(size_t)b * U + u] = h1;
            g_c1 [(size_t)b * U + u] = cl;
            g_out[(size_t)b * U + u] = hn;
        }
    }
}

__global__ __launch_bounds__(256) void cell0_kernel(const float* rg, const float* rb,
                                                    const float* sg, const float* sb,
                                                    const int* mask, int t)
{
    cell0_body(blockIdx.x, t, rg, rb, sg, sb, mask);
}

__global__ __launch_bounds__(256) void cell1_kernel(const float* kg, const float* kb,
                                                    const float* rg, const float* rb,
                                                    const float* sg, const float* sb,
                                                    const float* bias, const int* mask, int t)
{
    cell1_body(blockIdx.x, t, kg, kb, rg, rb, sg, sb, bias, mask);
}

// fused: blocks [0,B) do cell1(t); blocks [B,2B) do cell0(t+1)
__global__ __launch_bounds__(256) void fused_cell_kernel(
    const float* rg0, const float* rb0, const float* sg0, const float* sb0,
    const float* kg1, const float* kb1, const float* rg1, const float* rb1,
    const float* sg1, const float* sb1, const float* b1,
    const int* mask, int t)
{
    if (blockIdx.x < B)
        cell1_body(blockIdx.x, t, kg1, kb1, rg1, rb1, sg1, sb1, b1, mask);
    else
        cell0_body(blockIdx.x - B, t + 1, rg0, rb0, sg0, sb0, mask);
}

// ---------------- dense + softmax -----------------------------------------------------
__global__ __launch_bounds__(256) void dense_kernel(const float* __restrict__ Wd,
                                                    const float* __restrict__ bd,
                                                    float* __restrict__ out)
{
    const int b = blockIdx.x, tid = threadIdx.x, lane = tid & 31, w = tid >> 5;
    float p[NC];
#pragma unroll
    for (int c = 0; c < NC; c++) p[c] = 0.f;
    for (int u = tid; u < U; u += 256) {
        const float h = g_out[(size_t)b * U + u];
#pragma unroll
        for (int c = 0; c < NC; c++) p[c] += h * Wd[u * NC + c];
    }
    __shared__ float sh[NC][8];
#pragma unroll
    for (int c = 0; c < NC; c++) {
        float v = p[c];
#pragma unroll
        for (int o = 16; o > 0; o >>= 1) v += __shfl_xor_sync(0xffffffffu, v, o);
        if (lane == 0) sh[c][w] = v;
    }
    __syncthreads();
    if (tid == 0) {
        float lg[NC];
        float mx = -1e30f;
#pragma unroll
        for (int c = 0; c < NC; c++) {
            float l = bd[c];
#pragma unroll
            for (int i = 0; i < 8; i++) l += sh[c][i];
            lg[c] = l;
            mx = fmaxf(mx, l);
        }
        float sum = 0.f;
#pragma unroll
        for (int c = 0; c < NC; c++) { lg[c] = expf(lg[c] - mx); sum += lg[c]; }
        const float inv = 1.f / sum;
#pragma unroll
        for (int c = 0; c < NC; c++) out[b * NC + c] = lg[c] * inv;
    }
}

// ---------------- launch ---------------------------------------------------------------
extern "C" void kernel_launch(void* const* d_in, const int* in_sizes, int n_in,
                              void* d_out, int out_size)
{
    const float* x    = (const float*)d_in[0];
    const int*   mask = (const int*)  d_in[1];
    const float* W0   = (const float*)d_in[2];
    const float* R0   = (const float*)d_in[3];
    const float* b0   = (const float*)d_in[4];
    const float* kg0  = (const float*)d_in[5];
    const float* kb0  = (const float*)d_in[6];
    const float* rg0  = (const float*)d_in[7];
    const float* rb0  = (const float*)d_in[8];
    const float* sg0  = (const float*)d_in[9];
    const float* sb0  = (const float*)d_in[10];
    const float* W1   = (const float*)d_in[11];
    const float* R1   = (const float*)d_in[12];
    const float* b1   = (const float*)d_in[13];
    const float* kg1  = (const float*)d_in[14];
    const float* kb1  = (const float*)d_in[15];
    const float* rg1  = (const float*)d_in[16];
    const float* rb1  = (const float*)d_in[17];
    const float* sg1  = (const float*)d_in[18];
    const float* sb1  = (const float*)d_in[19];
    const float* Wd   = (const float*)d_in[20];
    const float* bd   = (const float*)d_in[21];
    float* out = (float*)d_out;

    float *A0p, *z0p, *z1ap, *z1bp;
    __half *x0, *x1, *W0a, *W0b, *R0a, *R0b, *W1a, *W1b, *R1a, *R1b;
    __half *h0sa, *h0sb, *h0ia, *h0ib, *h1sa, *h1sb;
    cudaGetSymbolAddress((void**)&A0p,  g_A0);
    cudaGetSymbolAddress((void**)&z0p,  g_z0);
    cudaGetSymbolAddress((void**)&z1ap, g_z1a);
    cudaGetSymbolAddress((void**)&z1bp, g_z1b);
    cudaGetSymbolAddress((void**)&x0,   g_x0);
    cudaGetSymbolAddress((void**)&x1,   g_x1);
    cudaGetSymbolAddress((void**)&W0a,  g_W0a);
    cudaGetSymbolAddress((void**)&W0b,  g_W0b);
    cudaGetSymbolAddress((void**)&R0a,  g_R0a);
    cudaGetSymbolAddress((void**)&R0b,  g_R0b);
    cudaGetSymbolAddress((void**)&W1a,  g_W1a);
    cudaGetSymbolAddress((void**)&W1b,  g_W1b);
    cudaGetSymbolAddress((void**)&R1a,  g_R1a);
    cudaGetSymbolAddress((void**)&R1b,  g_R1b);
    cudaGetSymbolAddress((void**)&h0sa, g_h0sa);
    cudaGetSymbolAddress((void**)&h0sb, g_h0sb);
    cudaGetSymbolAddress((void**)&h0ia, g_h0ia);
    cudaGetSymbolAddress((void**)&h0ib, g_h0ib);
    cudaGetSymbolAddress((void**)&h1sa, g_h1sa);
    cudaGetSymbolAddress((void**)&h1sb, g_h1sb);

    cudaFuncSetAttribute(gemm_f16x3, cudaFuncAttributeMaxDynamicSharedMemorySize, SMEM_H);

    // one-time prep
    const size_t nW0 = (size_t)G * KP;
    const size_t nRW = (size_t)G * U;
    const size_t nXT = (size_t)B * T * KP;
    init_kernel<<<(B * G + 255) / 256, 256>>>();
    wsplit2_t<<<(unsigned)((nW0 + 255) / 256), 256>>>(W0, W0a, W0b, KP, G, F);
    wsplit2_t<<<(unsigned)((nRW + 255) / 256), 256>>>(R0, R0a, R0b, U, G, U);
    wsplit2_t<<<(unsigned)((nRW + 255) / 256), 256>>>(W1, W1a, W1b, U, G, U);
    wsplit2_t<<<(unsigned)((nRW + 255) / 256), 256>>>(R1, R1a, R1b, U, G, U);
    xsplit2<<<(unsigned)((nXT + 255) / 256), 256>>>(x, x0, x1);

    // precompute A0 = LN(x @ W0)*kg0 + kb0 + b0
    {
        GArgsH a = {};
        a.p[0] = { x0, x1, W0a, W0b, A0p };
        gemm_f16x3<<<dim3(G / TNC, (B * T) / TMC, 1), 256, SMEM_H>>>(a, G, KP);
    }
    ln_rows_kernel<<<B * T, 256>>>(kg0, kb0, b0);

    // t = 0 prolog (z0(0) == 0)
    cell0_kernel<<<B, 256>>>(rg0, rb0, sg0, sb0, mask, 0);

    for (int t = 0; t < T - 1; t++) {
        GArgsH a = {};
        a.p[0] = { h0ia, h0ib, W1a, W1b, z1ap };   // z1a(t)
        a.p[1] = { h1sa, h1sb, R1a, R1b, z1bp };   // z1b(t)
        a.p[2] = { h0sa, h0sb, R0a, R0b, z0p  };   // z0(t+1)
        gemm_f16x3<<<dim3(G / TNC, B / TMC, 3), 256, SMEM_H>>>(a, G, U);
        fused_cell_kernel<<<2 * B, 256>>>(rg0, rb0, sg0, sb0,
                                          kg1, kb1, rg1, rb1, sg1, sb1, b1, mask, t);
    }

    // t = T-1 epilog
    {
        GArgsH a = {};
        a.p[0] = { h0ia, h0ib, W1a, W1b, z1ap };
        a.p[1] = { h1sa, h1sb, R1a, R1b, z1bp };
        gemm_f16x3<<<dim3(G / TNC, B / TMC, 2), 256, SMEM_H>>>(a, G, U);
        cell1_kernel<<<B, 256>>>(kg1, kb1, rg1, rb1, sg1, sb1, b1, mask, T - 1);
    }

    dense_kernel<<<B, 256>>>(Wd, bd, out);
}